// round 1
// baseline (speedup 1.0000x reference)
#include <cuda_runtime.h>

#define D_MODEL 2048
#define D_KV    512
#define HQ      16
#define DH      128
#define BATCH   2
#define TSEQ    2048
#define MROWS   (BATCH * TSEQ)   // 4096

// Scratch (allocation-free rule: __device__ globals)
__device__ float g_q[MROWS * D_MODEL];
__device__ float g_k[MROWS * D_KV];
__device__ float g_v[MROWS * D_KV];
__device__ float g_attn[MROWS * D_MODEL];

// ---------------------------------------------------------------------------
// SGEMM: C[M,N] = A[M,K] @ B[K,N] + bias[N]
// 128x128 block tile, BK=16, 256 threads, 8x8 per-thread register tile.
// Requires M%128==0, N%128==0, K%16==0 (true for all launches here).
// ---------------------------------------------------------------------------
__global__ void __launch_bounds__(256) sgemm_bias(
    const float* __restrict__ A, const float* __restrict__ B,
    const float* __restrict__ bias, float* __restrict__ C,
    int M, int N, int K)
{
    __shared__ float As[16][132];   // A tile transposed, padded stride
    __shared__ float Bs[16][128];

    const int tid = threadIdx.x;
    const int bx = blockIdx.x, by = blockIdx.y;
    const int ty = tid >> 4, tx = tid & 15;

    float acc[8][8];
    #pragma unroll
    for (int i = 0; i < 8; i++)
        #pragma unroll
        for (int j = 0; j < 8; j++) acc[i][j] = 0.f;

    const float* Ablk = A + (size_t)by * 128 * K;
    const float* Bblk = B + (size_t)bx * 128;

    for (int k0 = 0; k0 < K; k0 += 16) {
        #pragma unroll
        for (int u = 0; u < 2; u++) {
            int f  = tid + u * 256;
            int r  = f >> 2;
            int cg = (f & 3) << 2;
            float4 av = *(const float4*)(Ablk + (size_t)r * K + k0 + cg);
            As[cg + 0][r] = av.x;
            As[cg + 1][r] = av.y;
            As[cg + 2][r] = av.z;
            As[cg + 3][r] = av.w;
            int rb = f >> 5;
            int cb = (f & 31) << 2;
            *(float4*)(&Bs[rb][cb]) =
                *(const float4*)(Bblk + (size_t)(k0 + rb) * N + cb);
        }
        __syncthreads();
        #pragma unroll
        for (int kk = 0; kk < 16; kk++) {
            float a[8], b[8];
            #pragma unroll
            for (int i = 0; i < 8; i++) a[i] = As[kk][ty * 8 + i];
            #pragma unroll
            for (int j = 0; j < 8; j++) b[j] = Bs[kk][tx * 8 + j];
            #pragma unroll
            for (int i = 0; i < 8; i++)
                #pragma unroll
                for (int j = 0; j < 8; j++) acc[i][j] += a[i] * b[j];
        }
        __syncthreads();
    }

    float bvals[8];
    #pragma unroll
    for (int j = 0; j < 8; j++) bvals[j] = bias[bx * 128 + tx * 8 + j];
    #pragma unroll
    for (int i = 0; i < 8; i++) {
        float* cp = C + (size_t)(by * 128 + ty * 8 + i) * N + bx * 128 + tx * 8;
        #pragma unroll
        for (int j = 0; j < 8; j++) cp[j] = acc[i][j] + bvals[j];
    }
}

// ---------------------------------------------------------------------------
// Fused causal GQA attention (flash-style, online softmax).
// Q: [B*T, 2048] (head h at cols h*128), K/V: [B*T, 512] (kv head h/4).
// Block: 64 query rows of one head. 256 threads.
// ---------------------------------------------------------------------------
#define SM_QT   (128 * 65)
#define SM_KV   (128 * 65)         // K^T [128][65]  or  V [64][128]
#define SM_SS   (64 * 65)
#define ATTN_SMEM_FLOATS (SM_QT + SM_KV + SM_SS + 128)
#define ATTN_SMEM_BYTES  (ATTN_SMEM_FLOATS * 4)

__global__ void __launch_bounds__(256) attn_kernel(
    const float* __restrict__ Q, const float* __restrict__ K,
    const float* __restrict__ V, float* __restrict__ O)
{
    extern __shared__ float sm[];
    float* Qt   = sm;                    // [128][65]  Q transposed
    float* KV   = Qt + SM_QT;            // K^T [128][65] / V [64][128]
    float* Ss   = KV + SM_KV;            // [64][65]   scores / probs
    float* sc_s = Ss + SM_SS;            // [64] rescale factors
    float* l_s  = sc_s + 64;             // [64] denominators

    const int qb = blockIdx.x, h = blockIdx.y, bb = blockIdx.z;
    const int q0 = qb * 64;
    const int tid = threadIdx.x;
    const int ty = tid >> 4, tx = tid & 15;

    const float* qp    = Q + (size_t)(bb * TSEQ + q0) * D_MODEL + h * DH;
    const float* kbase = K + (size_t)(bb * TSEQ) * D_KV + (h >> 2) * DH;
    const float* vbase = V + (size_t)(bb * TSEQ) * D_KV + (h >> 2) * DH;

    // load Q tile transposed: Qt[d][r]
    for (int idx = tid; idx < 64 * 128; idx += 256) {
        int r = idx >> 7, d = idx & 127;
        Qt[d * 65 + r] = qp[(size_t)r * D_MODEL + d];
    }

    float o[4][8];
    #pragma unroll
    for (int i = 0; i < 4; i++)
        #pragma unroll
        for (int j = 0; j < 8; j++) o[i][j] = 0.f;

    float m_r = -1e30f, l_r = 0.f;   // per-row state (valid for tid < 64)

    for (int s0 = 0; s0 <= q0; s0 += 64) {
        __syncthreads();   // prev PV done (KV reusable); Qt ready (iter 0)

        // load K tile transposed: KV[d][r]
        const float* kp = kbase + (size_t)s0 * D_KV;
        for (int idx = tid; idx < 64 * 128; idx += 256) {
            int r = idx >> 7, d = idx & 127;
            KV[d * 65 + r] = kp[(size_t)r * D_KV + d];
        }
        __syncthreads();

        // S = Q K^T : each thread a 4x4 tile (rows ty*4.., cols tx*4..)
        float s_acc[4][4];
        #pragma unroll
        for (int i = 0; i < 4; i++)
            #pragma unroll
            for (int j = 0; j < 4; j++) s_acc[i][j] = 0.f;

        #pragma unroll 4
        for (int d = 0; d < 128; d++) {
            float qa[4], kb[4];
            #pragma unroll
            for (int i = 0; i < 4; i++) qa[i] = Qt[d * 65 + ty * 4 + i];
            #pragma unroll
            for (int j = 0; j < 4; j++) kb[j] = KV[d * 65 + tx * 4 + j];
            #pragma unroll
            for (int i = 0; i < 4; i++)
                #pragma unroll
                for (int j = 0; j < 4; j++) s_acc[i][j] += qa[i] * kb[j];
        }

        const float scl = 0.08838834764831845f;   // 1/sqrt(128)
        const bool diag = (s0 == q0);
        #pragma unroll
        for (int i = 0; i < 4; i++)
            #pragma unroll
            for (int j = 0; j < 4; j++) {
                int r = ty * 4 + i, c = tx * 4 + j;
                float v = s_acc[i][j] * scl;
                if (diag && c > r) v = -1e30f;    // causal mask (diag tile only)
                Ss[r * 65 + c] = v;
            }
        __syncthreads();

        // online softmax (one thread per row) while all threads stream V in
        if (tid < 64) {
            float mx = m_r;
            #pragma unroll 8
            for (int j = 0; j < 64; j++) mx = fmaxf(mx, Ss[tid * 65 + j]);
            float sum = 0.f;
            #pragma unroll 8
            for (int j = 0; j < 64; j++) {
                float p = __expf(Ss[tid * 65 + j] - mx);
                Ss[tid * 65 + j] = p;
                sum += p;
            }
            float sf = __expf(m_r - mx);
            l_r = l_r * sf + sum;
            m_r = mx;
            sc_s[tid] = sf;
        }
        // load V tile (overwrites K^T): KV[r][d], plain layout
        const float* vp = vbase + (size_t)s0 * D_KV;
        for (int idx = tid; idx < 64 * 128; idx += 256) {
            int r = idx >> 7, d = idx & 127;
            KV[r * 128 + d] = vp[(size_t)r * D_KV + d];
        }
        __syncthreads();

        // rescale O, then O += P @ V  (thread tile: rows ty*4.., cols tx*8..)
        #pragma unroll
        for (int i = 0; i < 4; i++) {
            float f = sc_s[ty * 4 + i];
            #pragma unroll
            for (int j = 0; j < 8; j++) o[i][j] *= f;
        }
        #pragma unroll 2
        for (int kk = 0; kk < 64; kk++) {
            float p[4];
            #pragma unroll
            for (int i = 0; i < 4; i++) p[i] = Ss[(ty * 4 + i) * 65 + kk];
            float4 v0 = *(const float4*)(&KV[kk * 128 + tx * 8]);
            float4 v1 = *(const float4*)(&KV[kk * 128 + tx * 8 + 4]);
            float vv[8] = {v0.x, v0.y, v0.z, v0.w, v1.x, v1.y, v1.z, v1.w};
            #pragma unroll
            for (int i = 0; i < 4; i++)
                #pragma unroll
                for (int j = 0; j < 8; j++) o[i][j] += p[i] * vv[j];
        }
    }

    if (tid < 64) l_s[tid] = l_r;
    __syncthreads();

    float* op = O + (size_t)(bb * TSEQ + q0) * D_MODEL + h * DH;
    #pragma unroll
    for (int i = 0; i < 4; i++) {
        float inv = 1.f / l_s[ty * 4 + i];
        #pragma unroll
        for (int j = 0; j < 8; j++)
            op[(size_t)(ty * 4 + i) * D_MODEL + tx * 8 + j] = o[i][j] * inv;
    }
}

// ---------------------------------------------------------------------------
extern "C" void kernel_launch(void* const* d_in, const int* in_sizes, int n_in,
                              void* d_out, int out_size)
{
    const float* x  = (const float*)d_in[0];
    const float* Wq = (const float*)d_in[1];
    const float* bq = (const float*)d_in[2];
    const float* Wk = (const float*)d_in[3];
    const float* bk = (const float*)d_in[4];
    const float* Wv = (const float*)d_in[5];
    const float* bv = (const float*)d_in[6];
    const float* Wo = (const float*)d_in[7];
    const float* bo = (const float*)d_in[8];
    float* out = (float*)d_out;

    float *qb_, *kb_, *vb_, *ab_;
    cudaGetSymbolAddress((void**)&qb_, g_q);
    cudaGetSymbolAddress((void**)&kb_, g_k);
    cudaGetSymbolAddress((void**)&vb_, g_v);
    cudaGetSymbolAddress((void**)&ab_, g_attn);

    cudaFuncSetAttribute(attn_kernel,
                         cudaFuncAttributeMaxDynamicSharedMemorySize,
                         ATTN_SMEM_BYTES);

    // Q, K, V projections
    sgemm_bias<<<dim3(D_MODEL / 128, MROWS / 128), 256>>>(
        x, Wq, bq, qb_, MROWS, D_MODEL, D_MODEL);
    sgemm_bias<<<dim3(D_KV / 128, MROWS / 128), 256>>>(
        x, Wk, bk, kb_, MROWS, D_KV, D_MODEL);
    sgemm_bias<<<dim3(D_KV / 128, MROWS / 128), 256>>>(
        x, Wv, bv, vb_, MROWS, D_KV, D_MODEL);

    // fused causal GQA attention
    attn_kernel<<<dim3(TSEQ / 64, HQ, BATCH), 256, ATTN_SMEM_BYTES>>>(
        qb_, kb_, vb_, ab_);

    // output projection
    sgemm_bias<<<dim3(D_MODEL / 128, MROWS / 128), 256>>>(
        ab_, Wo, bo, out, MROWS, D_MODEL, D_MODEL);
}

// round 2
// speedup vs baseline: 2.5016x; 2.5016x over previous
#include <cuda_runtime.h>
#include <cuda_bf16.h>
#include <cstdint>

#define D_MODEL 2048
#define D_KV    512
#define HQ      16
#define DH      128
#define BATCH   2
#define TSEQ    2048
#define MROWS   (BATCH * TSEQ)   // 4096

// ---------------- scratch (__device__ globals; no allocation allowed) -------
__device__ float g_q[MROWS * D_MODEL];
__device__ float g_k[MROWS * D_KV];
__device__ float g_v[MROWS * D_KV];
__device__ float g_attn[MROWS * D_MODEL];

__device__ __nv_bfloat16 g_xh[MROWS * D_MODEL];
__device__ __nv_bfloat16 g_xl[MROWS * D_MODEL];
__device__ __nv_bfloat16 g_wqh[D_MODEL * D_MODEL];
__device__ __nv_bfloat16 g_wql[D_MODEL * D_MODEL];
__device__ __nv_bfloat16 g_wkh[D_MODEL * D_KV];
__device__ __nv_bfloat16 g_wkl[D_MODEL * D_KV];
__device__ __nv_bfloat16 g_wvh[D_MODEL * D_KV];
__device__ __nv_bfloat16 g_wvl[D_MODEL * D_KV];
__device__ __nv_bfloat16 g_woh[D_MODEL * D_MODEL];
__device__ __nv_bfloat16 g_wol[D_MODEL * D_MODEL];
__device__ __nv_bfloat16 g_ah[MROWS * D_MODEL];
__device__ __nv_bfloat16 g_al[MROWS * D_MODEL];

// ---------------------------------------------------------------------------
// fp32 -> (bf16 hi, bf16 lo) split. n must be divisible by 4.
// ---------------------------------------------------------------------------
__global__ void __launch_bounds__(256) split_f32(
    const float* __restrict__ s, __nv_bfloat16* __restrict__ hi,
    __nv_bfloat16* __restrict__ lo, int n)
{
    int i = (blockIdx.x * blockDim.x + threadIdx.x) * 4;
    if (i >= n) return;
    float4 v = *(const float4*)(s + i);
    float f[4] = {v.x, v.y, v.z, v.w};
    __nv_bfloat16 h[4], l[4];
    #pragma unroll
    for (int j = 0; j < 4; j++) {
        h[j] = __float2bfloat16(f[j]);
        l[j] = __float2bfloat16(f[j] - __bfloat162float(h[j]));
    }
    ((__nv_bfloat162*)(hi + i))[0] = __nv_bfloat162(h[0], h[1]);
    ((__nv_bfloat162*)(hi + i))[1] = __nv_bfloat162(h[2], h[3]);
    ((__nv_bfloat162*)(lo + i))[0] = __nv_bfloat162(l[0], l[1]);
    ((__nv_bfloat162*)(lo + i))[1] = __nv_bfloat162(l[2], l[3]);
}

// ---------------------------------------------------------------------------
// Tensor-core GEMM with 2-term bf16 split (3 MMAs ~= fp32 accuracy).
// C[M,N] = A[M,K] @ B[K,N] + bias[N], A/B given as hi/lo bf16 pairs.
// Tile 128x128x32, 256 threads (8 warps, 2x4 warp grid, 64x32 per warp).
// cp.async double-buffered. Requires M%128==0, N%128==0, K%32==0.
// ---------------------------------------------------------------------------
#define BM 128
#define BN 128
#define BK 32
#define AST 40                        // A smem row stride (bf16) - bank-safe
#define BST 136                       // B smem row stride (bf16) - bank-safe
#define A_TILE (BM * AST)             // 5120 elems
#define B_TILE (BK * BST)             // 4352 elems
#define STAGE_ELEMS (2 * A_TILE + 2 * B_TILE)   // 18944
#define GEMM_SMEM_BYTES (2 * STAGE_ELEMS * 2)   // 75776 B

__device__ __forceinline__ uint32_t smem_u32(const void* p) {
    return (uint32_t)__cvta_generic_to_shared(p);
}
__device__ __forceinline__ void cp8(uint32_t d, const void* s) {
    asm volatile("cp.async.ca.shared.global [%0], [%1], 8;\n" :: "r"(d), "l"(s));
}
__device__ __forceinline__ void cp16(uint32_t d, const void* s) {
    asm volatile("cp.async.cg.shared.global [%0], [%1], 16;\n" :: "r"(d), "l"(s));
}
__device__ __forceinline__ void ldsm4(uint32_t* r, uint32_t a) {
    asm volatile("ldmatrix.sync.aligned.m8n8.x4.shared.b16 {%0,%1,%2,%3}, [%4];"
        : "=r"(r[0]), "=r"(r[1]), "=r"(r[2]), "=r"(r[3]) : "r"(a));
}
__device__ __forceinline__ void ldsm4t(uint32_t* r, uint32_t a) {
    asm volatile("ldmatrix.sync.aligned.m8n8.x4.trans.shared.b16 {%0,%1,%2,%3}, [%4];"
        : "=r"(r[0]), "=r"(r[1]), "=r"(r[2]), "=r"(r[3]) : "r"(a));
}
__device__ __forceinline__ void mma16816(float* d, const uint32_t* a,
                                         const uint32_t* b) {
    asm volatile(
        "mma.sync.aligned.m16n8k16.row.col.f32.bf16.bf16.f32 "
        "{%0,%1,%2,%3}, {%4,%5,%6,%7}, {%8,%9}, {%0,%1,%2,%3};"
        : "+f"(d[0]), "+f"(d[1]), "+f"(d[2]), "+f"(d[3])
        : "r"(a[0]), "r"(a[1]), "r"(a[2]), "r"(a[3]), "r"(b[0]), "r"(b[1]));
}

__global__ void __launch_bounds__(256) gemm_bf16x2(
    const __nv_bfloat16* __restrict__ Ah, const __nv_bfloat16* __restrict__ Al,
    const __nv_bfloat16* __restrict__ Bh, const __nv_bfloat16* __restrict__ Bl,
    const float* __restrict__ bias, float* __restrict__ C,
    int M, int N, int K)
{
    extern __shared__ __nv_bfloat16 sm[];
    const int tid = threadIdx.x;
    const int lane = tid & 31;
    const int wid = tid >> 5;
    const int wr = wid >> 2;          // 0..1
    const int wc = wid & 3;           // 0..3
    const int bx = blockIdx.x, by = blockIdx.y;
    const int am0 = by * BM;
    const int bn0 = bx * BN;

    float acc[4][4][4];
    #pragma unroll
    for (int mt = 0; mt < 4; mt++)
        #pragma unroll
        for (int nt = 0; nt < 4; nt++)
            #pragma unroll
            for (int e = 0; e < 4; e++) acc[mt][nt][e] = 0.f;

    auto load_stage = [&](int kt, int s) {
        const int k0 = kt * BK;
        __nv_bfloat16* base = sm + s * STAGE_ELEMS;
        // A hi/lo: 128 rows x 32 cols, 8B chunks
        #pragma unroll
        for (int i = 0; i < 4; i++) {
            int idx = tid + i * 256;
            int row = idx >> 3, ch = idx & 7;
            uint32_t d = smem_u32(base + row * AST + ch * 4);
            const __nv_bfloat16* sh = Ah + (size_t)(am0 + row) * K + k0 + ch * 4;
            const __nv_bfloat16* sl = Al + (size_t)(am0 + row) * K + k0 + ch * 4;
            cp8(d, sh);
            cp8(d + A_TILE * 2, sl);
        }
        // B hi/lo: 32 rows x 128 cols, 16B chunks
        #pragma unroll
        for (int i = 0; i < 2; i++) {
            int idx = tid + i * 256;
            int row = idx >> 4, ch = idx & 15;
            uint32_t d = smem_u32(base + 2 * A_TILE + row * BST + ch * 8);
            const __nv_bfloat16* sh = Bh + (size_t)(k0 + row) * N + bn0 + ch * 8;
            const __nv_bfloat16* sl = Bl + (size_t)(k0 + row) * N + bn0 + ch * 8;
            cp16(d, sh);
            cp16(d + B_TILE * 2, sl);
        }
        asm volatile("cp.async.commit_group;\n");
    };

    auto compute_stage = [&](int s) {
        __nv_bfloat16* base = sm + s * STAGE_ELEMS;
        const int sub = lane >> 3, r = lane & 7;
        #pragma unroll
        for (int ks = 0; ks < 2; ks++) {
            uint32_t ah[4][4], al[4][4], bh[2][4], bl[2][4];
            #pragma unroll
            for (int mt = 0; mt < 4; mt++) {
                int row = wr * 64 + mt * 16 + ((sub & 1) << 3) + r;
                int col = ks * 16 + ((sub >> 1) << 3);
                uint32_t a = smem_u32(base + row * AST + col);
                ldsm4(ah[mt], a);
                ldsm4(al[mt], a + A_TILE * 2);
            }
            #pragma unroll
            for (int ng = 0; ng < 2; ng++) {
                int krow = ks * 16 + ((sub & 1) << 3) + r;
                int ncol = wc * 32 + ng * 16 + ((sub >> 1) << 3);
                uint32_t b = smem_u32(base + 2 * A_TILE + krow * BST + ncol);
                ldsm4t(bh[ng], b);
                ldsm4t(bl[ng], b + B_TILE * 2);
            }
            #pragma unroll
            for (int mt = 0; mt < 4; mt++)
                #pragma unroll
                for (int nt = 0; nt < 4; nt++) {
                    int ng = nt >> 1, o = (nt & 1) * 2;
                    mma16816(acc[mt][nt], ah[mt], &bh[ng][o]);
                    mma16816(acc[mt][nt], ah[mt], &bl[ng][o]);
                    mma16816(acc[mt][nt], al[mt], &bh[ng][o]);
                }
        }
    };

    const int ktot = K / BK;
    load_stage(0, 0);
    for (int kt = 0; kt < ktot; kt++) {
        if (kt + 1 < ktot) {
            load_stage(kt + 1, (kt + 1) & 1);
            asm volatile("cp.async.wait_group 1;\n");
        } else {
            asm volatile("cp.async.wait_group 0;\n");
        }
        __syncthreads();
        compute_stage(kt & 1);
        __syncthreads();
    }

    // epilogue: D frag rows lane/4, lane/4+8; cols (lane%4)*2, +1
    const int rbase = am0 + wr * 64;
    const int cbase = bn0 + wc * 32;
    #pragma unroll
    for (int mt = 0; mt < 4; mt++) {
        int r0 = rbase + mt * 16 + (lane >> 2);
        #pragma unroll
        for (int nt = 0; nt < 4; nt++) {
            int c = cbase + nt * 8 + (lane & 3) * 2;
            float b0 = bias[c], b1 = bias[c + 1];
            float2 v0 = make_float2(acc[mt][nt][0] + b0, acc[mt][nt][1] + b1);
            float2 v1 = make_float2(acc[mt][nt][2] + b0, acc[mt][nt][3] + b1);
            *(float2*)(C + (size_t)r0 * N + c) = v0;
            *(float2*)(C + (size_t)(r0 + 8) * N + c) = v1;
        }
    }
}

// ---------------------------------------------------------------------------
// Fused causal GQA attention (unchanged from round 1, fp32).
// ---------------------------------------------------------------------------
#define SM_QT   (128 * 65)
#define SM_KV   (128 * 65)
#define SM_SS   (64 * 65)
#define ATTN_SMEM_FLOATS (SM_QT + SM_KV + SM_SS + 128)
#define ATTN_SMEM_BYTES  (ATTN_SMEM_FLOATS * 4)

__global__ void __launch_bounds__(256) attn_kernel(
    const float* __restrict__ Q, const float* __restrict__ K,
    const float* __restrict__ V, float* __restrict__ O)
{
    extern __shared__ float smf[];
    float* Qt   = smf;
    float* KV   = Qt + SM_QT;
    float* Ss   = KV + SM_KV;
    float* sc_s = Ss + SM_SS;
    float* l_s  = sc_s + 64;

    const int qb = blockIdx.x, h = blockIdx.y, bb = blockIdx.z;
    const int q0 = qb * 64;
    const int tid = threadIdx.x;
    const int ty = tid >> 4, tx = tid & 15;

    const float* qp    = Q + (size_t)(bb * TSEQ + q0) * D_MODEL + h * DH;
    const float* kbase = K + (size_t)(bb * TSEQ) * D_KV + (h >> 2) * DH;
    const float* vbase = V + (size_t)(bb * TSEQ) * D_KV + (h >> 2) * DH;

    for (int idx = tid; idx < 64 * 128; idx += 256) {
        int r = idx >> 7, d = idx & 127;
        Qt[d * 65 + r] = qp[(size_t)r * D_MODEL + d];
    }

    float o[4][8];
    #pragma unroll
    for (int i = 0; i < 4; i++)
        #pragma unroll
        for (int j = 0; j < 8; j++) o[i][j] = 0.f;

    float m_r = -1e30f, l_r = 0.f;

    for (int s0 = 0; s0 <= q0; s0 += 64) {
        __syncthreads();
        const float* kp = kbase + (size_t)s0 * D_KV;
        for (int idx = tid; idx < 64 * 128; idx += 256) {
            int r = idx >> 7, d = idx & 127;
            KV[d * 65 + r] = kp[(size_t)r * D_KV + d];
        }
        __syncthreads();

        float s_acc[4][4];
        #pragma unroll
        for (int i = 0; i < 4; i++)
            #pragma unroll
            for (int j = 0; j < 4; j++) s_acc[i][j] = 0.f;

        #pragma unroll 4
        for (int d = 0; d < 128; d++) {
            float qa[4], kb[4];
            #pragma unroll
            for (int i = 0; i < 4; i++) qa[i] = Qt[d * 65 + ty * 4 + i];
            #pragma unroll
            for (int j = 0; j < 4; j++) kb[j] = KV[d * 65 + tx * 4 + j];
            #pragma unroll
            for (int i = 0; i < 4; i++)
                #pragma unroll
                for (int j = 0; j < 4; j++) s_acc[i][j] += qa[i] * kb[j];
        }

        const float scl = 0.08838834764831845f;
        const bool diag = (s0 == q0);
        #pragma unroll
        for (int i = 0; i < 4; i++)
            #pragma unroll
            for (int j = 0; j < 4; j++) {
                int r = ty * 4 + i, c = tx * 4 + j;
                float v = s_acc[i][j] * scl;
                if (diag && c > r) v = -1e30f;
                Ss[r * 65 + c] = v;
            }
        __syncthreads();

        if (tid < 64) {
            float mx = m_r;
            #pragma unroll 8
            for (int j = 0; j < 64; j++) mx = fmaxf(mx, Ss[tid * 65 + j]);
            float sum = 0.f;
            #pragma unroll 8
            for (int j = 0; j < 64; j++) {
                float p = __expf(Ss[tid * 65 + j] - mx);
                Ss[tid * 65 + j] = p;
                sum += p;
            }
            float sf = __expf(m_r - mx);
            l_r = l_r * sf + sum;
            m_r = mx;
            sc_s[tid] = sf;
        }
        const float* vp = vbase + (size_t)s0 * D_KV;
        for (int idx = tid; idx < 64 * 128; idx += 256) {
            int r = idx >> 7, d = idx & 127;
            KV[r * 128 + d] = vp[(size_t)r * D_KV + d];
        }
        __syncthreads();

        #pragma unroll
        for (int i = 0; i < 4; i++) {
            float f = sc_s[ty * 4 + i];
            #pragma unroll
            for (int j = 0; j < 8; j++) o[i][j] *= f;
        }
        #pragma unroll 2
        for (int kk = 0; kk < 64; kk++) {
            float p[4];
            #pragma unroll
            for (int i = 0; i < 4; i++) p[i] = Ss[(ty * 4 + i) * 65 + kk];
            float4 v0 = *(const float4*)(&KV[kk * 128 + tx * 8]);
            float4 v1 = *(const float4*)(&KV[kk * 128 + tx * 8 + 4]);
            float vv[8] = {v0.x, v0.y, v0.z, v0.w, v1.x, v1.y, v1.z, v1.w};
            #pragma unroll
            for (int i = 0; i < 4; i++)
                #pragma unroll
                for (int j = 0; j < 8; j++) o[i][j] += p[i] * vv[j];
        }
    }

    if (tid < 64) l_s[tid] = l_r;
    __syncthreads();

    float* op = O + (size_t)(bb * TSEQ + q0) * D_MODEL + h * DH;
    #pragma unroll
    for (int i = 0; i < 4; i++) {
        float inv = 1.f / l_s[ty * 4 + i];
        #pragma unroll
        for (int j = 0; j < 8; j++)
            op[(size_t)(ty * 4 + i) * D_MODEL + tx * 8 + j] = o[i][j] * inv;
    }
}

// ---------------------------------------------------------------------------
extern "C" void kernel_launch(void* const* d_in, const int* in_sizes, int n_in,
                              void* d_out, int out_size)
{
    const float* x  = (const float*)d_in[0];
    const float* Wq = (const float*)d_in[1];
    const float* bq = (const float*)d_in[2];
    const float* Wk = (const float*)d_in[3];
    const float* bk = (const float*)d_in[4];
    const float* Wv = (const float*)d_in[5];
    const float* bv = (const float*)d_in[6];
    const float* Wo = (const float*)d_in[7];
    const float* bo = (const float*)d_in[8];
    float* out = (float*)d_out;

    float *qb_, *kb_, *vb_, *ab_;
    cudaGetSymbolAddress((void**)&qb_, g_q);
    cudaGetSymbolAddress((void**)&kb_, g_k);
    cudaGetSymbolAddress((void**)&vb_, g_v);
    cudaGetSymbolAddress((void**)&ab_, g_attn);

    __nv_bfloat16 *xh, *xl, *wqh, *wql, *wkh, *wkl, *wvh, *wvl, *woh, *wol, *ah, *al;
    cudaGetSymbolAddress((void**)&xh, g_xh);
    cudaGetSymbolAddress((void**)&xl, g_xl);
    cudaGetSymbolAddress((void**)&wqh, g_wqh);
    cudaGetSymbolAddress((void**)&wql, g_wql);
    cudaGetSymbolAddress((void**)&wkh, g_wkh);
    cudaGetSymbolAddress((void**)&wkl, g_wkl);
    cudaGetSymbolAddress((void**)&wvh, g_wvh);
    cudaGetSymbolAddress((void**)&wvl, g_wvl);
    cudaGetSymbolAddress((void**)&woh, g_woh);
    cudaGetSymbolAddress((void**)&wol, g_wol);
    cudaGetSymbolAddress((void**)&ah, g_ah);
    cudaGetSymbolAddress((void**)&al, g_al);

    cudaFuncSetAttribute(attn_kernel,
                         cudaFuncAttributeMaxDynamicSharedMemorySize,
                         ATTN_SMEM_BYTES);
    cudaFuncSetAttribute(gemm_bf16x2,
                         cudaFuncAttributeMaxDynamicSharedMemorySize,
                         GEMM_SMEM_BYTES);

    // split inputs into hi/lo bf16
    {
        int n;
        n = MROWS * D_MODEL;   split_f32<<<n / 4 / 256, 256>>>(x,  xh,  xl,  n);
        n = D_MODEL * D_MODEL; split_f32<<<n / 4 / 256, 256>>>(Wq, wqh, wql, n);
        n = D_MODEL * D_KV;    split_f32<<<n / 4 / 256, 256>>>(Wk, wkh, wkl, n);
        n = D_MODEL * D_KV;    split_f32<<<n / 4 / 256, 256>>>(Wv, wvh, wvl, n);
        n = D_MODEL * D_MODEL; split_f32<<<n / 4 / 256, 256>>>(Wo, woh, wol, n);
    }

    // projections on tensor cores
    gemm_bf16x2<<<dim3(D_MODEL / BN, MROWS / BM), 256, GEMM_SMEM_BYTES>>>(
        xh, xl, wqh, wql, bq, qb_, MROWS, D_MODEL, D_MODEL);
    gemm_bf16x2<<<dim3(D_KV / BN, MROWS / BM), 256, GEMM_SMEM_BYTES>>>(
        xh, xl, wkh, wkl, bk, kb_, MROWS, D_KV, D_MODEL);
    gemm_bf16x2<<<dim3(D_KV / BN, MROWS / BM), 256, GEMM_SMEM_BYTES>>>(
        xh, xl, wvh, wvl, bv, vb_, MROWS, D_KV, D_MODEL);

    // fused causal GQA attention (fp32)
    attn_kernel<<<dim3(TSEQ / 64, HQ, BATCH), 256, ATTN_SMEM_BYTES>>>(
        qb_, kb_, vb_, ab_);

    // split attention output, then O projection on tensor cores
    {
        int n = MROWS * D_MODEL;
        split_f32<<<n / 4 / 256, 256>>>(ab_, ah, al, n);
    }
    gemm_bf16x2<<<dim3(D_MODEL / BN, MROWS / BM), 256, GEMM_SMEM_BYTES>>>(
        ah, al, woh, wol, bo, out, MROWS, D_MODEL, D_MODEL);
}

// round 3
// speedup vs baseline: 4.9114x; 1.9633x over previous
#include <cuda_runtime.h>
#include <cuda_bf16.h>
#include <cstdint>

#define D_MODEL 2048
#define D_KV    512
#define HQ      16
#define DH      128
#define BATCH   2
#define TSEQ    2048
#define MROWS   (BATCH * TSEQ)   // 4096

// ---------------- scratch (__device__ globals; no allocation allowed) -------
__device__ __nv_bfloat16 g_xh[MROWS * D_MODEL];
__device__ __nv_bfloat16 g_xl[MROWS * D_MODEL];
__device__ __nv_bfloat16 g_wqh[D_MODEL * D_MODEL];
__device__ __nv_bfloat16 g_wql[D_MODEL * D_MODEL];
__device__ __nv_bfloat16 g_wkh[D_MODEL * D_KV];
__device__ __nv_bfloat16 g_wkl[D_MODEL * D_KV];
__device__ __nv_bfloat16 g_wvh[D_MODEL * D_KV];
__device__ __nv_bfloat16 g_wvl[D_MODEL * D_KV];
__device__ __nv_bfloat16 g_woh[D_MODEL * D_MODEL];
__device__ __nv_bfloat16 g_wol[D_MODEL * D_MODEL];

__device__ __nv_bfloat16 g_qh[MROWS * D_MODEL];
__device__ __nv_bfloat16 g_ql[MROWS * D_MODEL];
__device__ __nv_bfloat16 g_kh[MROWS * D_KV];
__device__ __nv_bfloat16 g_kl[MROWS * D_KV];
__device__ __nv_bfloat16 g_vh[MROWS * D_KV];
__device__ __nv_bfloat16 g_vl[MROWS * D_KV];
__device__ __nv_bfloat16 g_ah[MROWS * D_MODEL];
__device__ __nv_bfloat16 g_al[MROWS * D_MODEL];

// ---------------------------------------------------------------------------
__global__ void __launch_bounds__(256) split_f32(
    const float* __restrict__ s, __nv_bfloat16* __restrict__ hi,
    __nv_bfloat16* __restrict__ lo, int n)
{
    int i = (blockIdx.x * blockDim.x + threadIdx.x) * 4;
    if (i >= n) return;
    float4 v = *(const float4*)(s + i);
    float f[4] = {v.x, v.y, v.z, v.w};
    __nv_bfloat16 h[4], l[4];
    #pragma unroll
    for (int j = 0; j < 4; j++) {
        h[j] = __float2bfloat16(f[j]);
        l[j] = __float2bfloat16(f[j] - __bfloat162float(h[j]));
    }
    ((__nv_bfloat162*)(hi + i))[0] = __nv_bfloat162(h[0], h[1]);
    ((__nv_bfloat162*)(hi + i))[1] = __nv_bfloat162(h[2], h[3]);
    ((__nv_bfloat162*)(lo + i))[0] = __nv_bfloat162(l[0], l[1]);
    ((__nv_bfloat162*)(lo + i))[1] = __nv_bfloat162(l[2], l[3]);
}

// ---------------------------------------------------------------------------
// helpers
// ---------------------------------------------------------------------------
__device__ __forceinline__ uint32_t smem_u32(const void* p) {
    return (uint32_t)__cvta_generic_to_shared(p);
}
__device__ __forceinline__ void cp8(uint32_t d, const void* s) {
    asm volatile("cp.async.ca.shared.global [%0], [%1], 8;\n" :: "r"(d), "l"(s));
}
__device__ __forceinline__ void cp16(uint32_t d, const void* s) {
    asm volatile("cp.async.cg.shared.global [%0], [%1], 16;\n" :: "r"(d), "l"(s));
}
__device__ __forceinline__ void ldsm4(uint32_t* r, uint32_t a) {
    asm volatile("ldmatrix.sync.aligned.m8n8.x4.shared.b16 {%0,%1,%2,%3}, [%4];"
        : "=r"(r[0]), "=r"(r[1]), "=r"(r[2]), "=r"(r[3]) : "r"(a));
}
__device__ __forceinline__ void ldsm4t(uint32_t* r, uint32_t a) {
    asm volatile("ldmatrix.sync.aligned.m8n8.x4.trans.shared.b16 {%0,%1,%2,%3}, [%4];"
        : "=r"(r[0]), "=r"(r[1]), "=r"(r[2]), "=r"(r[3]) : "r"(a));
}
__device__ __forceinline__ void mma16816(float* d, const uint32_t* a,
                                         uint32_t b0, uint32_t b1) {
    asm volatile(
        "mma.sync.aligned.m16n8k16.row.col.f32.bf16.bf16.f32 "
        "{%0,%1,%2,%3}, {%4,%5,%6,%7}, {%8,%9}, {%0,%1,%2,%3};"
        : "+f"(d[0]), "+f"(d[1]), "+f"(d[2]), "+f"(d[3])
        : "r"(a[0]), "r"(a[1]), "r"(a[2]), "r"(a[3]), "r"(b0), "r"(b1));
}
__device__ __forceinline__ uint32_t pack_bf2(float x, float y) {
    __nv_bfloat162 t(__float2bfloat16(x), __float2bfloat16(y));
    return *(uint32_t*)&t;
}

// ---------------------------------------------------------------------------
// Tensor-core GEMM, 2-term bf16 split. OUT_MODE 0: fp32 C. 1: bf16 hi/lo C.
// Tile 128x128x32, 256 threads. Requires M%128==0, N%128==0, K%32==0.
// ---------------------------------------------------------------------------
#define BM 128
#define BN 128
#define BK 32
#define AST 40
#define BST 136
#define A_TILE (BM * AST)
#define B_TILE (BK * BST)
#define STAGE_ELEMS (2 * A_TILE + 2 * B_TILE)
#define GEMM_SMEM_BYTES (2 * STAGE_ELEMS * 2)

template<int OUT_MODE>
__global__ void __launch_bounds__(256) gemm_bf16x2(
    const __nv_bfloat16* __restrict__ Ah, const __nv_bfloat16* __restrict__ Al,
    const __nv_bfloat16* __restrict__ Bh, const __nv_bfloat16* __restrict__ Bl,
    const float* __restrict__ bias, float* __restrict__ C,
    __nv_bfloat16* __restrict__ Ch, __nv_bfloat16* __restrict__ Cl,
    int M, int N, int K)
{
    extern __shared__ __nv_bfloat16 sm[];
    const int tid = threadIdx.x;
    const int lane = tid & 31;
    const int wid = tid >> 5;
    const int wr = wid >> 2;
    const int wc = wid & 3;
    const int am0 = blockIdx.y * BM;
    const int bn0 = blockIdx.x * BN;

    float acc[4][4][4];
    #pragma unroll
    for (int mt = 0; mt < 4; mt++)
        #pragma unroll
        for (int nt = 0; nt < 4; nt++)
            #pragma unroll
            for (int e = 0; e < 4; e++) acc[mt][nt][e] = 0.f;

    auto load_stage = [&](int kt, int s) {
        const int k0 = kt * BK;
        __nv_bfloat16* base = sm + s * STAGE_ELEMS;
        #pragma unroll
        for (int i = 0; i < 4; i++) {
            int idx = tid + i * 256;
            int row = idx >> 3, ch = idx & 7;
            uint32_t d = smem_u32(base + row * AST + ch * 4);
            cp8(d, Ah + (size_t)(am0 + row) * K + k0 + ch * 4);
            cp8(d + A_TILE * 2, Al + (size_t)(am0 + row) * K + k0 + ch * 4);
        }
        #pragma unroll
        for (int i = 0; i < 2; i++) {
            int idx = tid + i * 256;
            int row = idx >> 4, ch = idx & 15;
            uint32_t d = smem_u32(base + 2 * A_TILE + row * BST + ch * 8);
            cp16(d, Bh + (size_t)(k0 + row) * N + bn0 + ch * 8);
            cp16(d + B_TILE * 2, Bl + (size_t)(k0 + row) * N + bn0 + ch * 8);
        }
        asm volatile("cp.async.commit_group;\n");
    };

    auto compute_stage = [&](int s) {
        __nv_bfloat16* base = sm + s * STAGE_ELEMS;
        const int sub = lane >> 3, r = lane & 7;
        #pragma unroll
        for (int ks = 0; ks < 2; ks++) {
            uint32_t ah[4][4], al[4][4], bh[2][4], bl[2][4];
            #pragma unroll
            for (int mt = 0; mt < 4; mt++) {
                int row = wr * 64 + mt * 16 + ((sub & 1) << 3) + r;
                int col = ks * 16 + ((sub >> 1) << 3);
                uint32_t a = smem_u32(base + row * AST + col);
                ldsm4(ah[mt], a);
                ldsm4(al[mt], a + A_TILE * 2);
            }
            #pragma unroll
            for (int ng = 0; ng < 2; ng++) {
                int krow = ks * 16 + ((sub & 1) << 3) + r;
                int ncol = wc * 32 + ng * 16 + ((sub >> 1) << 3);
                uint32_t b = smem_u32(base + 2 * A_TILE + krow * BST + ncol);
                ldsm4t(bh[ng], b);
                ldsm4t(bl[ng], b + B_TILE * 2);
            }
            #pragma unroll
            for (int mt = 0; mt < 4; mt++)
                #pragma unroll
                for (int nt = 0; nt < 4; nt++) {
                    int ng = nt >> 1, o = (nt & 1) * 2;
                    mma16816(acc[mt][nt], ah[mt], bh[ng][o], bh[ng][o + 1]);
                    mma16816(acc[mt][nt], ah[mt], bl[ng][o], bl[ng][o + 1]);
                    mma16816(acc[mt][nt], al[mt], bh[ng][o], bh[ng][o + 1]);
                }
        }
    };

    const int ktot = K / BK;
    load_stage(0, 0);
    for (int kt = 0; kt < ktot; kt++) {
        if (kt + 1 < ktot) {
            load_stage(kt + 1, (kt + 1) & 1);
            asm volatile("cp.async.wait_group 1;\n");
        } else {
            asm volatile("cp.async.wait_group 0;\n");
        }
        __syncthreads();
        compute_stage(kt & 1);
        __syncthreads();
    }

    const int rbase = am0 + wr * 64;
    const int cbase = bn0 + wc * 32;
    #pragma unroll
    for (int mt = 0; mt < 4; mt++) {
        int r0 = rbase + mt * 16 + (lane >> 2);
        #pragma unroll
        for (int nt = 0; nt < 4; nt++) {
            int c = cbase + nt * 8 + (lane & 3) * 2;
            float b0 = bias[c], b1 = bias[c + 1];
            float v00 = acc[mt][nt][0] + b0, v01 = acc[mt][nt][1] + b1;
            float v10 = acc[mt][nt][2] + b0, v11 = acc[mt][nt][3] + b1;
            if (OUT_MODE == 0) {
                *(float2*)(C + (size_t)r0 * N + c) = make_float2(v00, v01);
                *(float2*)(C + (size_t)(r0 + 8) * N + c) = make_float2(v10, v11);
            } else {
                __nv_bfloat16 h00 = __float2bfloat16(v00);
                __nv_bfloat16 h01 = __float2bfloat16(v01);
                __nv_bfloat16 h10 = __float2bfloat16(v10);
                __nv_bfloat16 h11 = __float2bfloat16(v11);
                *(__nv_bfloat162*)(Ch + (size_t)r0 * N + c) = __nv_bfloat162(h00, h01);
                *(__nv_bfloat162*)(Ch + (size_t)(r0 + 8) * N + c) = __nv_bfloat162(h10, h11);
                *(__nv_bfloat162*)(Cl + (size_t)r0 * N + c) = __nv_bfloat162(
                    __float2bfloat16(v00 - __bfloat162float(h00)),
                    __float2bfloat16(v01 - __bfloat162float(h01)));
                *(__nv_bfloat162*)(Cl + (size_t)(r0 + 8) * N + c) = __nv_bfloat162(
                    __float2bfloat16(v10 - __bfloat162float(h10)),
                    __float2bfloat16(v11 - __bfloat162float(h11)));
            }
        }
    }
}

// ---------------------------------------------------------------------------
// Tensor-core fused causal GQA attention.
// Br=128 (8 warps x 16 rows), Bc=64, Dh=128, hi/lo split everywhere.
// ---------------------------------------------------------------------------
#define KST 136
#define Q_ELEMS (128 * KST)
#define KV_ELEMS (64 * KST)
#define ATT_STAGE (4 * KV_ELEMS)     // Kh,Kl,Vh,Vl
#define ATT_SMEM_BYTES ((2 * Q_ELEMS + 2 * ATT_STAGE) * 2)   // 208896

__global__ void __launch_bounds__(256) attn_mma(
    const __nv_bfloat16* __restrict__ Qh, const __nv_bfloat16* __restrict__ Ql,
    const __nv_bfloat16* __restrict__ Kh, const __nv_bfloat16* __restrict__ Kl,
    const __nv_bfloat16* __restrict__ Vh, const __nv_bfloat16* __restrict__ Vl,
    __nv_bfloat16* __restrict__ Oh, __nv_bfloat16* __restrict__ Ol)
{
    extern __shared__ __nv_bfloat16 sm[];
    __nv_bfloat16* sQh = sm;
    __nv_bfloat16* sQl = sQh + Q_ELEMS;
    __nv_bfloat16* sKV = sQl + Q_ELEMS;    // [stage][Kh|Kl|Vh|Vl]

    const int qb = (int)gridDim.x - 1 - (int)blockIdx.x;   // heavy blocks first
    const int h = blockIdx.y, bb = blockIdx.z;
    const int q0 = qb * 128;
    const int tid = threadIdx.x;
    const int lane = tid & 31;
    const int w = tid >> 5;

    const size_t qoff = (size_t)(bb * TSEQ + q0) * D_MODEL + h * DH;
    const size_t kvoff = (size_t)(bb * TSEQ) * D_KV + (h >> 2) * DH;

    // ---- load Q (hi/lo) ----
    #pragma unroll
    for (int i = 0; i < 8; i++) {
        int idx = tid + i * 256;
        int row = idx >> 4, ch = idx & 15;
        uint32_t d = smem_u32(sQh + row * KST + ch * 8);
        cp16(d, Qh + qoff + (size_t)row * D_MODEL + ch * 8);
        cp16(d + Q_ELEMS * 2, Ql + qoff + (size_t)row * D_MODEL + ch * 8);
    }
    asm volatile("cp.async.commit_group;\n");

    const int ntiles = 2 * qb + 2;

    auto load_kv = [&](int t, int s) {
        __nv_bfloat16* base = sKV + s * ATT_STAGE;
        const size_t goff = kvoff + (size_t)(t * 64) * D_KV;
        #pragma unroll
        for (int i = 0; i < 4; i++) {
            int idx = tid + i * 256;
            int row = idx >> 4, ch = idx & 15;
            uint32_t d = smem_u32(base + row * KST + ch * 8);
            size_t g = goff + (size_t)row * D_KV + ch * 8;
            cp16(d, Kh + g);
            cp16(d + KV_ELEMS * 2, Kl + g);
            cp16(d + 2 * KV_ELEMS * 2, Vh + g);
            cp16(d + 3 * KV_ELEMS * 2, Vl + g);
        }
        asm volatile("cp.async.commit_group;\n");
    };

    load_kv(0, 0);

    float oacc[16][4];
    #pragma unroll
    for (int nt = 0; nt < 16; nt++)
        #pragma unroll
        for (int e = 0; e < 4; e++) oacc[nt][e] = 0.f;
    float m0 = -1e30f, m1 = -1e30f, l0 = 0.f, l1 = 0.f;

    const int r0g = q0 + w * 16 + (lane >> 2);  // global row of elems 0,1
    const int r1g = r0g + 8;
    const float scl = 0.08838834764831845f;     // 1/sqrt(128)

    for (int t = 0; t < ntiles; t++) {
        if (t + 1 < ntiles) {
            load_kv(t + 1, (t + 1) & 1);
            asm volatile("cp.async.wait_group 1;\n");
        } else {
            asm volatile("cp.async.wait_group 0;\n");
        }
        __syncthreads();

        const int s0 = t * 64;
        const bool warp_active = (s0 <= q0 + w * 16 + 15);
        if (warp_active) {
            __nv_bfloat16* base = sKV + (t & 1) * ATT_STAGE;
            __nv_bfloat16* bKh = base;
            __nv_bfloat16* bVh = base + 2 * KV_ELEMS;

            // ---- S = Q K^T ----
            float sacc[8][4];
            #pragma unroll
            for (int nt = 0; nt < 8; nt++)
                #pragma unroll
                for (int e = 0; e < 4; e++) sacc[nt][e] = 0.f;

            #pragma unroll
            for (int kc = 0; kc < 8; kc++) {
                uint32_t qa_h[4], qa_l[4];
                {
                    int row = w * 16 + (lane & 15);
                    int col = kc * 16 + ((lane >> 4) << 3);
                    uint32_t a = smem_u32(sQh + row * KST + col);
                    ldsm4(qa_h, a);
                    ldsm4(qa_l, a + Q_ELEMS * 2);
                }
                #pragma unroll
                for (int nb = 0; nb < 4; nb++) {
                    uint32_t kb_h[4], kb_l[4];
                    int row = nb * 16 + (lane & 15);
                    int col = kc * 16 + ((lane >> 4) << 3);
                    uint32_t a = smem_u32(bKh + row * KST + col);
                    ldsm4(kb_h, a);
                    ldsm4(kb_l, a + KV_ELEMS * 2);
                    // ntile 2nb uses {r0,r2}; 2nb+1 uses {r1,r3}
                    mma16816(sacc[2 * nb], qa_h, kb_h[0], kb_h[2]);
                    mma16816(sacc[2 * nb], qa_h, kb_l[0], kb_l[2]);
                    mma16816(sacc[2 * nb], qa_l, kb_h[0], kb_h[2]);
                    mma16816(sacc[2 * nb + 1], qa_h, kb_h[1], kb_h[3]);
                    mma16816(sacc[2 * nb + 1], qa_h, kb_l[1], kb_l[3]);
                    mma16816(sacc[2 * nb + 1], qa_l, kb_h[1], kb_h[3]);
                }
            }

            // ---- scale + causal mask ----
            const bool need_mask = (s0 + 63 > q0 + w * 16);
            #pragma unroll
            for (int nt = 0; nt < 8; nt++) {
                int cg = s0 + nt * 8 + (lane & 3) * 2;
                #pragma unroll
                for (int e = 0; e < 4; e++) sacc[nt][e] *= scl;
                if (need_mask) {
                    if (cg > r0g)     sacc[nt][0] = -1e30f;
                    if (cg + 1 > r0g) sacc[nt][1] = -1e30f;
                    if (cg > r1g)     sacc[nt][2] = -1e30f;
                    if (cg + 1 > r1g) sacc[nt][3] = -1e30f;
                }
            }

            // ---- online softmax (registers) ----
            float mx0 = -1e30f, mx1 = -1e30f;
            #pragma unroll
            for (int nt = 0; nt < 8; nt++) {
                mx0 = fmaxf(mx0, fmaxf(sacc[nt][0], sacc[nt][1]));
                mx1 = fmaxf(mx1, fmaxf(sacc[nt][2], sacc[nt][3]));
            }
            mx0 = fmaxf(mx0, __shfl_xor_sync(0xffffffffu, mx0, 1));
            mx0 = fmaxf(mx0, __shfl_xor_sync(0xffffffffu, mx0, 2));
            mx1 = fmaxf(mx1, __shfl_xor_sync(0xffffffffu, mx1, 1));
            mx1 = fmaxf(mx1, __shfl_xor_sync(0xffffffffu, mx1, 2));
            float nm0 = fmaxf(m0, mx0), nm1 = fmaxf(m1, mx1);
            float a0 = __expf(m0 - nm0), a1 = __expf(m1 - nm1);

            float sum0 = 0.f, sum1 = 0.f;
            #pragma unroll
            for (int nt = 0; nt < 8; nt++) {
                sacc[nt][0] = __expf(sacc[nt][0] - nm0);
                sacc[nt][1] = __expf(sacc[nt][1] - nm0);
                sacc[nt][2] = __expf(sacc[nt][2] - nm1);
                sacc[nt][3] = __expf(sacc[nt][3] - nm1);
                sum0 += sacc[nt][0] + sacc[nt][1];
                sum1 += sacc[nt][2] + sacc[nt][3];
            }
            sum0 += __shfl_xor_sync(0xffffffffu, sum0, 1);
            sum0 += __shfl_xor_sync(0xffffffffu, sum0, 2);
            sum1 += __shfl_xor_sync(0xffffffffu, sum1, 1);
            sum1 += __shfl_xor_sync(0xffffffffu, sum1, 2);
            l0 = l0 * a0 + sum0;
            l1 = l1 * a1 + sum1;
            m0 = nm0;
            m1 = nm1;

            #pragma unroll
            for (int nt = 0; nt < 16; nt++) {
                oacc[nt][0] *= a0;
                oacc[nt][1] *= a0;
                oacc[nt][2] *= a1;
                oacc[nt][3] *= a1;
            }

            // ---- O += P V ----
            const int sub = lane >> 3, r = lane & 7;
            #pragma unroll
            for (int kc2 = 0; kc2 < 4; kc2++) {
                const int n0 = 2 * kc2, n1 = n0 + 1;
                uint32_t pah[4], pal[4];
                {
                    float p00 = sacc[n0][0], p01 = sacc[n0][1];
                    float p02 = sacc[n0][2], p03 = sacc[n0][3];
                    float p10 = sacc[n1][0], p11 = sacc[n1][1];
                    float p12 = sacc[n1][2], p13 = sacc[n1][3];
                    uint32_t h0 = pack_bf2(p00, p01), h1 = pack_bf2(p02, p03);
                    uint32_t h2 = pack_bf2(p10, p11), h3 = pack_bf2(p12, p13);
                    pah[0] = h0; pah[1] = h1; pah[2] = h2; pah[3] = h3;
                    __nv_bfloat162 t0 = *(__nv_bfloat162*)&h0;
                    __nv_bfloat162 t1 = *(__nv_bfloat162*)&h1;
                    __nv_bfloat162 t2 = *(__nv_bfloat162*)&h2;
                    __nv_bfloat162 t3 = *(__nv_bfloat162*)&h3;
                    pal[0] = pack_bf2(p00 - __bfloat162float(t0.x),
                                      p01 - __bfloat162float(t0.y));
                    pal[1] = pack_bf2(p02 - __bfloat162float(t1.x),
                                      p03 - __bfloat162float(t1.y));
                    pal[2] = pack_bf2(p10 - __bfloat162float(t2.x),
                                      p11 - __bfloat162float(t2.y));
                    pal[3] = pack_bf2(p12 - __bfloat162float(t3.x),
                                      p13 - __bfloat162float(t3.y));
                }
                #pragma unroll
                for (int ntb = 0; ntb < 8; ntb++) {
                    uint32_t vh4[4], vl4[4];
                    int row = kc2 * 16 + ((sub & 1) << 3) + r;
                    int col = ntb * 16 + ((sub >> 1) << 3);
                    uint32_t a = smem_u32(bVh + row * KST + col);
                    ldsm4t(vh4, a);
                    ldsm4t(vl4, a + KV_ELEMS * 2);
                    mma16816(oacc[2 * ntb], pah, vh4[0], vh4[1]);
                    mma16816(oacc[2 * ntb], pah, vl4[0], vl4[1]);
                    mma16816(oacc[2 * ntb], pal, vh4[0], vh4[1]);
                    mma16816(oacc[2 * ntb + 1], pah, vh4[2], vh4[3]);
                    mma16816(oacc[2 * ntb + 1], pah, vl4[2], vl4[3]);
                    mma16816(oacc[2 * ntb + 1], pal, vh4[2], vh4[3]);
                }
            }
        }
        __syncthreads();
    }

    // ---- epilogue: O / l -> bf16 hi/lo ----
    float inv0 = 1.f / l0, inv1 = 1.f / l1;
    size_t row0 = qoff + (size_t)(w * 16 + (lane >> 2)) * D_MODEL;
    size_t row1 = row0 + (size_t)8 * D_MODEL;
    #pragma unroll
    for (int nt = 0; nt < 16; nt++) {
        int c = nt * 8 + (lane & 3) * 2;
        float v00 = oacc[nt][0] * inv0, v01 = oacc[nt][1] * inv0;
        float v10 = oacc[nt][2] * inv1, v11 = oacc[nt][3] * inv1;
        __nv_bfloat16 h00 = __float2bfloat16(v00);
        __nv_bfloat16 h01 = __float2bfloat16(v01);
        __nv_bfloat16 h10 = __float2bfloat16(v10);
        __nv_bfloat16 h11 = __float2bfloat16(v11);
        *(__nv_bfloat162*)(Oh + row0 + c) = __nv_bfloat162(h00, h01);
        *(__nv_bfloat162*)(Oh + row1 + c) = __nv_bfloat162(h10, h11);
        *(__nv_bfloat162*)(Ol + row0 + c) = __nv_bfloat162(
            __float2bfloat16(v00 - __bfloat162float(h00)),
            __float2bfloat16(v01 - __bfloat162float(h01)));
        *(__nv_bfloat162*)(Ol + row1 + c) = __nv_bfloat162(
            __float2bfloat16(v10 - __bfloat162float(h10)),
            __float2bfloat16(v11 - __bfloat162float(h11)));
    }
}

// ---------------------------------------------------------------------------
extern "C" void kernel_launch(void* const* d_in, const int* in_sizes, int n_in,
                              void* d_out, int out_size)
{
    const float* x  = (const float*)d_in[0];
    const float* Wq = (const float*)d_in[1];
    const float* bq = (const float*)d_in[2];
    const float* Wk = (const float*)d_in[3];
    const float* bk = (const float*)d_in[4];
    const float* Wv = (const float*)d_in[5];
    const float* bv = (const float*)d_in[6];
    const float* Wo = (const float*)d_in[7];
    const float* bo = (const float*)d_in[8];
    float* out = (float*)d_out;

    __nv_bfloat16 *xh, *xl, *wqh, *wql, *wkh, *wkl, *wvh, *wvl, *woh, *wol;
    __nv_bfloat16 *qh, *ql, *kh, *kl, *vh, *vl, *ah, *al;
    cudaGetSymbolAddress((void**)&xh, g_xh);
    cudaGetSymbolAddress((void**)&xl, g_xl);
    cudaGetSymbolAddress((void**)&wqh, g_wqh);
    cudaGetSymbolAddress((void**)&wql, g_wql);
    cudaGetSymbolAddress((void**)&wkh, g_wkh);
    cudaGetSymbolAddress((void**)&wkl, g_wkl);
    cudaGetSymbolAddress((void**)&wvh, g_wvh);
    cudaGetSymbolAddress((void**)&wvl, g_wvl);
    cudaGetSymbolAddress((void**)&woh, g_woh);
    cudaGetSymbolAddress((void**)&wol, g_wol);
    cudaGetSymbolAddress((void**)&qh, g_qh);
    cudaGetSymbolAddress((void**)&ql, g_ql);
    cudaGetSymbolAddress((void**)&kh, g_kh);
    cudaGetSymbolAddress((void**)&kl, g_kl);
    cudaGetSymbolAddress((void**)&vh, g_vh);
    cudaGetSymbolAddress((void**)&vl, g_vl);
    cudaGetSymbolAddress((void**)&ah, g_ah);
    cudaGetSymbolAddress((void**)&al, g_al);

    cudaFuncSetAttribute(gemm_bf16x2<0>,
                         cudaFuncAttributeMaxDynamicSharedMemorySize,
                         GEMM_SMEM_BYTES);
    cudaFuncSetAttribute(gemm_bf16x2<1>,
                         cudaFuncAttributeMaxDynamicSharedMemorySize,
                         GEMM_SMEM_BYTES);
    cudaFuncSetAttribute(attn_mma,
                         cudaFuncAttributeMaxDynamicSharedMemorySize,
                         ATT_SMEM_BYTES);

    // split inputs into hi/lo bf16
    {
        int n;
        n = MROWS * D_MODEL;   split_f32<<<n / 4 / 256, 256>>>(x,  xh,  xl,  n);
        n = D_MODEL * D_MODEL; split_f32<<<n / 4 / 256, 256>>>(Wq, wqh, wql, n);
        n = D_MODEL * D_KV;    split_f32<<<n / 4 / 256, 256>>>(Wk, wkh, wkl, n);
        n = D_MODEL * D_KV;    split_f32<<<n / 4 / 256, 256>>>(Wv, wvh, wvl, n);
        n = D_MODEL * D_MODEL; split_f32<<<n / 4 / 256, 256>>>(Wo, woh, wol, n);
    }

    // projections -> bf16 hi/lo directly
    gemm_bf16x2<1><<<dim3(D_MODEL / BN, MROWS / BM), 256, GEMM_SMEM_BYTES>>>(
        xh, xl, wqh, wql, bq, nullptr, qh, ql, MROWS, D_MODEL, D_MODEL);
    gemm_bf16x2<1><<<dim3(D_KV / BN, MROWS / BM), 256, GEMM_SMEM_BYTES>>>(
        xh, xl, wkh, wkl, bk, nullptr, kh, kl, MROWS, D_KV, D_MODEL);
    gemm_bf16x2<1><<<dim3(D_KV / BN, MROWS / BM), 256, GEMM_SMEM_BYTES>>>(
        xh, xl, wvh, wvl, bv, nullptr, vh, vl, MROWS, D_KV, D_MODEL);

    // fused causal GQA attention on tensor cores
    attn_mma<<<dim3(TSEQ / 128, HQ, BATCH), 256, ATT_SMEM_BYTES>>>(
        qh, ql, kh, kl, vh, vl, ah, al);

    // output projection -> fp32 out
    gemm_bf16x2<0><<<dim3(D_MODEL / BN, MROWS / BM), 256, GEMM_SMEM_BYTES>>>(
        ah, al, woh, wol, bo, out, nullptr, nullptr, MROWS, D_MODEL, D_MODEL);
}

// round 4
// speedup vs baseline: 5.1207x; 1.0426x over previous
#include <cuda_runtime.h>
#include <cuda_bf16.h>
#include <cstdint>

#define D_MODEL 2048
#define D_KV    512
#define HQ      16
#define DH      128
#define BATCH   2
#define TSEQ    2048
#define MROWS   (BATCH * TSEQ)   // 4096

// ---------------- scratch (__device__ globals; no allocation allowed) -------
__device__ __nv_bfloat16 g_xh[MROWS * D_MODEL];
__device__ __nv_bfloat16 g_xl[MROWS * D_MODEL];
__device__ __nv_bfloat16 g_wqh[D_MODEL * D_MODEL];
__device__ __nv_bfloat16 g_wql[D_MODEL * D_MODEL];
__device__ __nv_bfloat16 g_wkh[D_MODEL * D_KV];
__device__ __nv_bfloat16 g_wkl[D_MODEL * D_KV];
__device__ __nv_bfloat16 g_wvh[D_MODEL * D_KV];
__device__ __nv_bfloat16 g_wvl[D_MODEL * D_KV];
__device__ __nv_bfloat16 g_woh[D_MODEL * D_MODEL];
__device__ __nv_bfloat16 g_wol[D_MODEL * D_MODEL];

__device__ __nv_bfloat16 g_qh[MROWS * D_MODEL];
__device__ __nv_bfloat16 g_ql[MROWS * D_MODEL];
__device__ __nv_bfloat16 g_kh[MROWS * D_KV];
__device__ __nv_bfloat16 g_kl[MROWS * D_KV];
__device__ __nv_bfloat16 g_vh[MROWS * D_KV];
__device__ __nv_bfloat16 g_vl[MROWS * D_KV];
__device__ __nv_bfloat16 g_ah[MROWS * D_MODEL];
__device__ __nv_bfloat16 g_al[MROWS * D_MODEL];

// ---------------------------------------------------------------------------
__global__ void __launch_bounds__(256) split_f32(
    const float* __restrict__ s, __nv_bfloat16* __restrict__ hi,
    __nv_bfloat16* __restrict__ lo, int n)
{
    int i = (blockIdx.x * blockDim.x + threadIdx.x) * 4;
    if (i >= n) return;
    float4 v = *(const float4*)(s + i);
    float f[4] = {v.x, v.y, v.z, v.w};
    __nv_bfloat16 h[4], l[4];
    #pragma unroll
    for (int j = 0; j < 4; j++) {
        h[j] = __float2bfloat16(f[j]);
        l[j] = __float2bfloat16(f[j] - __bfloat162float(h[j]));
    }
    ((__nv_bfloat162*)(hi + i))[0] = __nv_bfloat162(h[0], h[1]);
    ((__nv_bfloat162*)(hi + i))[1] = __nv_bfloat162(h[2], h[3]);
    ((__nv_bfloat162*)(lo + i))[0] = __nv_bfloat162(l[0], l[1]);
    ((__nv_bfloat162*)(lo + i))[1] = __nv_bfloat162(l[2], l[3]);
}

// ---------------------------------------------------------------------------
// helpers
// ---------------------------------------------------------------------------
__device__ __forceinline__ uint32_t smem_u32(const void* p) {
    return (uint32_t)__cvta_generic_to_shared(p);
}
__device__ __forceinline__ void cp16(uint32_t d, const void* s) {
    asm volatile("cp.async.cg.shared.global [%0], [%1], 16;\n" :: "r"(d), "l"(s));
}
__device__ __forceinline__ void ldsm4(uint32_t* r, uint32_t a) {
    asm volatile("ldmatrix.sync.aligned.m8n8.x4.shared.b16 {%0,%1,%2,%3}, [%4];"
        : "=r"(r[0]), "=r"(r[1]), "=r"(r[2]), "=r"(r[3]) : "r"(a));
}
__device__ __forceinline__ void ldsm4t(uint32_t* r, uint32_t a) {
    asm volatile("ldmatrix.sync.aligned.m8n8.x4.trans.shared.b16 {%0,%1,%2,%3}, [%4];"
        : "=r"(r[0]), "=r"(r[1]), "=r"(r[2]), "=r"(r[3]) : "r"(a));
}
__device__ __forceinline__ void mma16816(float* d, const uint32_t* a,
                                         uint32_t b0, uint32_t b1) {
    asm volatile(
        "mma.sync.aligned.m16n8k16.row.col.f32.bf16.bf16.f32 "
        "{%0,%1,%2,%3}, {%4,%5,%6,%7}, {%8,%9}, {%0,%1,%2,%3};"
        : "+f"(d[0]), "+f"(d[1]), "+f"(d[2]), "+f"(d[3])
        : "r"(a[0]), "r"(a[1]), "r"(a[2]), "r"(a[3]), "r"(b0), "r"(b1));
}
__device__ __forceinline__ uint32_t pack_bf2(float x, float y) {
    __nv_bfloat162 t(__float2bfloat16(x), __float2bfloat16(y));
    return *(uint32_t*)&t;
}

// ---------------------------------------------------------------------------
// GEMM core: 2-term bf16 split, 128x128x32 tile, 3-stage cp.async pipeline,
// one __syncthreads per k-iteration. 256 threads.
// OUT_MODE 0: fp32 C + bias.  OUT_MODE 1: bf16 hi/lo C + bias.
// ---------------------------------------------------------------------------
#define BM 128
#define BN 128
#define BK 32
#define AST 40
#define BST 136
#define A_TILE (BM * AST)
#define B_TILE (BK * BST)
#define STAGE_ELEMS (2 * A_TILE + 2 * B_TILE)      // 18944
#define GEMM_STAGES 3
#define GEMM_SMEM_BYTES (GEMM_STAGES * STAGE_ELEMS * 2)   // 113664

template<int OUT_MODE>
__device__ __forceinline__ void gemm_core(
    const __nv_bfloat16* __restrict__ Ah, const __nv_bfloat16* __restrict__ Al,
    const __nv_bfloat16* __restrict__ Bh, const __nv_bfloat16* __restrict__ Bl,
    const float* __restrict__ bias, float* __restrict__ C,
    __nv_bfloat16* __restrict__ Ch, __nv_bfloat16* __restrict__ Cl,
    int N, int K, int am0, int bn0, __nv_bfloat16* sm)
{
    const int tid = threadIdx.x;
    const int lane = tid & 31;
    const int wid = tid >> 5;
    const int wr = wid >> 2;
    const int wc = wid & 3;

    float acc[4][4][4];
    #pragma unroll
    for (int mt = 0; mt < 4; mt++)
        #pragma unroll
        for (int nt = 0; nt < 4; nt++)
            #pragma unroll
            for (int e = 0; e < 4; e++) acc[mt][nt][e] = 0.f;

    auto load_stage = [&](int kt, int s) {
        const int k0 = kt * BK;
        __nv_bfloat16* base = sm + s * STAGE_ELEMS;
        // A hi/lo: 128x32, 16B chunks (4 per row)
        #pragma unroll
        for (int i = 0; i < 2; i++) {
            int idx = tid + i * 256;
            int row = idx >> 2, ch = idx & 3;
            uint32_t d = smem_u32(base + row * AST + ch * 8);
            const size_t g = (size_t)(am0 + row) * K + k0 + ch * 8;
            cp16(d, Ah + g);
            cp16(d + A_TILE * 2, Al + g);
        }
        // B hi/lo: 32x128, 16B chunks (16 per row)
        #pragma unroll
        for (int i = 0; i < 2; i++) {
            int idx = tid + i * 256;
            int row = idx >> 4, ch = idx & 15;
            uint32_t d = smem_u32(base + 2 * A_TILE + row * BST + ch * 8);
            const size_t g = (size_t)(k0 + row) * N + bn0 + ch * 8;
            cp16(d, Bh + g);
            cp16(d + B_TILE * 2, Bl + g);
        }
    };

    auto compute_stage = [&](int s) {
        __nv_bfloat16* base = sm + s * STAGE_ELEMS;
        const int sub = lane >> 3, r = lane & 7;
        #pragma unroll
        for (int ks = 0; ks < 2; ks++) {
            uint32_t ah[4][4], al[4][4], bh[2][4], bl[2][4];
            #pragma unroll
            for (int mt = 0; mt < 4; mt++) {
                int row = wr * 64 + mt * 16 + ((sub & 1) << 3) + r;
                int col = ks * 16 + ((sub >> 1) << 3);
                uint32_t a = smem_u32(base + row * AST + col);
                ldsm4(ah[mt], a);
                ldsm4(al[mt], a + A_TILE * 2);
            }
            #pragma unroll
            for (int ng = 0; ng < 2; ng++) {
                int krow = ks * 16 + ((sub & 1) << 3) + r;
                int ncol = wc * 32 + ng * 16 + ((sub >> 1) << 3);
                uint32_t b = smem_u32(base + 2 * A_TILE + krow * BST + ncol);
                ldsm4t(bh[ng], b);
                ldsm4t(bl[ng], b + B_TILE * 2);
            }
            #pragma unroll
            for (int mt = 0; mt < 4; mt++)
                #pragma unroll
                for (int nt = 0; nt < 4; nt++) {
                    int ng = nt >> 1, o = (nt & 1) * 2;
                    mma16816(acc[mt][nt], ah[mt], bh[ng][o], bh[ng][o + 1]);
                    mma16816(acc[mt][nt], ah[mt], bl[ng][o], bl[ng][o + 1]);
                    mma16816(acc[mt][nt], al[mt], bh[ng][o], bh[ng][o + 1]);
                }
        }
    };

    const int ktot = K / BK;
    load_stage(0, 0);
    asm volatile("cp.async.commit_group;\n");
    load_stage(1, 1);
    asm volatile("cp.async.commit_group;\n");

    int s_comp = 0, s_load = 2;
    for (int kt = 0; kt < ktot; kt++) {
        asm volatile("cp.async.wait_group 1;\n");
        __syncthreads();
        if (kt + 2 < ktot) load_stage(kt + 2, s_load);
        asm volatile("cp.async.commit_group;\n");
        compute_stage(s_comp);
        s_comp = (s_comp == GEMM_STAGES - 1) ? 0 : s_comp + 1;
        s_load = (s_load == GEMM_STAGES - 1) ? 0 : s_load + 1;
    }

    const int rbase = am0 + wr * 64;
    const int cbase = bn0 + wc * 32;
    #pragma unroll
    for (int mt = 0; mt < 4; mt++) {
        int r0 = rbase + mt * 16 + (lane >> 2);
        #pragma unroll
        for (int nt = 0; nt < 4; nt++) {
            int c = cbase + nt * 8 + (lane & 3) * 2;
            float b0 = bias[c], b1 = bias[c + 1];
            float v00 = acc[mt][nt][0] + b0, v01 = acc[mt][nt][1] + b1;
            float v10 = acc[mt][nt][2] + b0, v11 = acc[mt][nt][3] + b1;
            if (OUT_MODE == 0) {
                *(float2*)(C + (size_t)r0 * N + c) = make_float2(v00, v01);
                *(float2*)(C + (size_t)(r0 + 8) * N + c) = make_float2(v10, v11);
            } else {
                __nv_bfloat16 h00 = __float2bfloat16(v00);
                __nv_bfloat16 h01 = __float2bfloat16(v01);
                __nv_bfloat16 h10 = __float2bfloat16(v10);
                __nv_bfloat16 h11 = __float2bfloat16(v11);
                *(__nv_bfloat162*)(Ch + (size_t)r0 * N + c) = __nv_bfloat162(h00, h01);
                *(__nv_bfloat162*)(Ch + (size_t)(r0 + 8) * N + c) = __nv_bfloat162(h10, h11);
                *(__nv_bfloat162*)(Cl + (size_t)r0 * N + c) = __nv_bfloat162(
                    __float2bfloat16(v00 - __bfloat162float(h00)),
                    __float2bfloat16(v01 - __bfloat162float(h01)));
                *(__nv_bfloat162*)(Cl + (size_t)(r0 + 8) * N + c) = __nv_bfloat162(
                    __float2bfloat16(v10 - __bfloat162float(h10)),
                    __float2bfloat16(v11 - __bfloat162float(h11)));
            }
        }
    }
}

// Fused QKV projection: grid.x = 16 (Q) + 4 (K) + 4 (V) column blocks.
__global__ void __launch_bounds__(256, 2) gemm_qkv(
    const __nv_bfloat16* __restrict__ xh, const __nv_bfloat16* __restrict__ xl,
    const __nv_bfloat16* __restrict__ wqh, const __nv_bfloat16* __restrict__ wql,
    const __nv_bfloat16* __restrict__ wkh, const __nv_bfloat16* __restrict__ wkl,
    const __nv_bfloat16* __restrict__ wvh, const __nv_bfloat16* __restrict__ wvl,
    const float* __restrict__ bq, const float* __restrict__ bk,
    const float* __restrict__ bv,
    __nv_bfloat16* __restrict__ qh, __nv_bfloat16* __restrict__ ql,
    __nv_bfloat16* __restrict__ kh, __nv_bfloat16* __restrict__ kl,
    __nv_bfloat16* __restrict__ vh, __nv_bfloat16* __restrict__ vl)
{
    extern __shared__ __nv_bfloat16 sm[];
    const int bx = blockIdx.x;
    const int am0 = blockIdx.y * BM;
    if (bx < 16) {
        gemm_core<1>(xh, xl, wqh, wql, bq, nullptr, qh, ql,
                     D_MODEL, D_MODEL, am0, bx * BN, sm);
    } else if (bx < 20) {
        gemm_core<1>(xh, xl, wkh, wkl, bk, nullptr, kh, kl,
                     D_KV, D_MODEL, am0, (bx - 16) * BN, sm);
    } else {
        gemm_core<1>(xh, xl, wvh, wvl, bv, nullptr, vh, vl,
                     D_KV, D_MODEL, am0, (bx - 20) * BN, sm);
    }
}

// Output projection -> fp32
__global__ void __launch_bounds__(256, 2) gemm_out(
    const __nv_bfloat16* __restrict__ ah, const __nv_bfloat16* __restrict__ al,
    const __nv_bfloat16* __restrict__ woh, const __nv_bfloat16* __restrict__ wol,
    const float* __restrict__ bo, float* __restrict__ out)
{
    extern __shared__ __nv_bfloat16 sm[];
    gemm_core<0>(ah, al, woh, wol, bo, out, nullptr, nullptr,
                 D_MODEL, D_MODEL, blockIdx.y * BM, blockIdx.x * BN, sm);
}

// ---------------------------------------------------------------------------
// Tensor-core fused causal GQA attention (unchanged from round 3).
// ---------------------------------------------------------------------------
#define KST 136
#define Q_ELEMS (128 * KST)
#define KV_ELEMS (64 * KST)
#define ATT_STAGE (4 * KV_ELEMS)
#define ATT_SMEM_BYTES ((2 * Q_ELEMS + 2 * ATT_STAGE) * 2)

__global__ void __launch_bounds__(256) attn_mma(
    const __nv_bfloat16* __restrict__ Qh, const __nv_bfloat16* __restrict__ Ql,
    const __nv_bfloat16* __restrict__ Kh, const __nv_bfloat16* __restrict__ Kl,
    const __nv_bfloat16* __restrict__ Vh, const __nv_bfloat16* __restrict__ Vl,
    __nv_bfloat16* __restrict__ Oh, __nv_bfloat16* __restrict__ Ol)
{
    extern __shared__ __nv_bfloat16 sm[];
    __nv_bfloat16* sQh = sm;
    __nv_bfloat16* sQl = sQh + Q_ELEMS;
    __nv_bfloat16* sKV = sQl + Q_ELEMS;

    const int qb = (int)gridDim.x - 1 - (int)blockIdx.x;
    const int h = blockIdx.y, bb = blockIdx.z;
    const int q0 = qb * 128;
    const int tid = threadIdx.x;
    const int lane = tid & 31;
    const int w = tid >> 5;

    const size_t qoff = (size_t)(bb * TSEQ + q0) * D_MODEL + h * DH;
    const size_t kvoff = (size_t)(bb * TSEQ) * D_KV + (h >> 2) * DH;

    #pragma unroll
    for (int i = 0; i < 8; i++) {
        int idx = tid + i * 256;
        int row = idx >> 4, ch = idx & 15;
        uint32_t d = smem_u32(sQh + row * KST + ch * 8);
        cp16(d, Qh + qoff + (size_t)row * D_MODEL + ch * 8);
        cp16(d + Q_ELEMS * 2, Ql + qoff + (size_t)row * D_MODEL + ch * 8);
    }
    asm volatile("cp.async.commit_group;\n");

    const int ntiles = 2 * qb + 2;

    auto load_kv = [&](int t, int s) {
        __nv_bfloat16* base = sKV + s * ATT_STAGE;
        const size_t goff = kvoff + (size_t)(t * 64) * D_KV;
        #pragma unroll
        for (int i = 0; i < 4; i++) {
            int idx = tid + i * 256;
            int row = idx >> 4, ch = idx & 15;
            uint32_t d = smem_u32(base + row * KST + ch * 8);
            size_t g = goff + (size_t)row * D_KV + ch * 8;
            cp16(d, Kh + g);
            cp16(d + KV_ELEMS * 2, Kl + g);
            cp16(d + 2 * KV_ELEMS * 2, Vh + g);
            cp16(d + 3 * KV_ELEMS * 2, Vl + g);
        }
        asm volatile("cp.async.commit_group;\n");
    };

    load_kv(0, 0);

    float oacc[16][4];
    #pragma unroll
    for (int nt = 0; nt < 16; nt++)
        #pragma unroll
        for (int e = 0; e < 4; e++) oacc[nt][e] = 0.f;
    float m0 = -1e30f, m1 = -1e30f, l0 = 0.f, l1 = 0.f;

    const int r0g = q0 + w * 16 + (lane >> 2);
    const int r1g = r0g + 8;
    const float scl = 0.08838834764831845f;

    for (int t = 0; t < ntiles; t++) {
        if (t + 1 < ntiles) {
            load_kv(t + 1, (t + 1) & 1);
            asm volatile("cp.async.wait_group 1;\n");
        } else {
            asm volatile("cp.async.wait_group 0;\n");
        }
        __syncthreads();

        const int s0 = t * 64;
        const bool warp_active = (s0 <= q0 + w * 16 + 15);
        if (warp_active) {
            __nv_bfloat16* base = sKV + (t & 1) * ATT_STAGE;
            __nv_bfloat16* bKh = base;
            __nv_bfloat16* bVh = base + 2 * KV_ELEMS;

            float sacc[8][4];
            #pragma unroll
            for (int nt = 0; nt < 8; nt++)
                #pragma unroll
                for (int e = 0; e < 4; e++) sacc[nt][e] = 0.f;

            #pragma unroll
            for (int kc = 0; kc < 8; kc++) {
                uint32_t qa_h[4], qa_l[4];
                {
                    int row = w * 16 + (lane & 15);
                    int col = kc * 16 + ((lane >> 4) << 3);
                    uint32_t a = smem_u32(sQh + row * KST + col);
                    ldsm4(qa_h, a);
                    ldsm4(qa_l, a + Q_ELEMS * 2);
                }
                #pragma unroll
                for (int nb = 0; nb < 4; nb++) {
                    uint32_t kb_h[4], kb_l[4];
                    int row = nb * 16 + (lane & 15);
                    int col = kc * 16 + ((lane >> 4) << 3);
                    uint32_t a = smem_u32(bKh + row * KST + col);
                    ldsm4(kb_h, a);
                    ldsm4(kb_l, a + KV_ELEMS * 2);
                    mma16816(sacc[2 * nb], qa_h, kb_h[0], kb_h[2]);
                    mma16816(sacc[2 * nb], qa_h, kb_l[0], kb_l[2]);
                    mma16816(sacc[2 * nb], qa_l, kb_h[0], kb_h[2]);
                    mma16816(sacc[2 * nb + 1], qa_h, kb_h[1], kb_h[3]);
                    mma16816(sacc[2 * nb + 1], qa_h, kb_l[1], kb_l[3]);
                    mma16816(sacc[2 * nb + 1], qa_l, kb_h[1], kb_h[3]);
                }
            }

            const bool need_mask = (s0 + 63 > q0 + w * 16);
            #pragma unroll
            for (int nt = 0; nt < 8; nt++) {
                int cg = s0 + nt * 8 + (lane & 3) * 2;
                #pragma unroll
                for (int e = 0; e < 4; e++) sacc[nt][e] *= scl;
                if (need_mask) {
                    if (cg > r0g)     sacc[nt][0] = -1e30f;
                    if (cg + 1 > r0g) sacc[nt][1] = -1e30f;
                    if (cg > r1g)     sacc[nt][2] = -1e30f;
                    if (cg + 1 > r1g) sacc[nt][3] = -1e30f;
                }
            }

            float mx0 = -1e30f, mx1 = -1e30f;
            #pragma unroll
            for (int nt = 0; nt < 8; nt++) {
                mx0 = fmaxf(mx0, fmaxf(sacc[nt][0], sacc[nt][1]));
                mx1 = fmaxf(mx1, fmaxf(sacc[nt][2], sacc[nt][3]));
            }
            mx0 = fmaxf(mx0, __shfl_xor_sync(0xffffffffu, mx0, 1));
            mx0 = fmaxf(mx0, __shfl_xor_sync(0xffffffffu, mx0, 2));
            mx1 = fmaxf(mx1, __shfl_xor_sync(0xffffffffu, mx1, 1));
            mx1 = fmaxf(mx1, __shfl_xor_sync(0xffffffffu, mx1, 2));
            float nm0 = fmaxf(m0, mx0), nm1 = fmaxf(m1, mx1);
            float a0 = __expf(m0 - nm0), a1 = __expf(m1 - nm1);

            float sum0 = 0.f, sum1 = 0.f;
            #pragma unroll
            for (int nt = 0; nt < 8; nt++) {
                sacc[nt][0] = __expf(sacc[nt][0] - nm0);
                sacc[nt][1] = __expf(sacc[nt][1] - nm0);
                sacc[nt][2] = __expf(sacc[nt][2] - nm1);
                sacc[nt][3] = __expf(sacc[nt][3] - nm1);
                sum0 += sacc[nt][0] + sacc[nt][1];
                sum1 += sacc[nt][2] + sacc[nt][3];
            }
            sum0 += __shfl_xor_sync(0xffffffffu, sum0, 1);
            sum0 += __shfl_xor_sync(0xffffffffu, sum0, 2);
            sum1 += __shfl_xor_sync(0xffffffffu, sum1, 1);
            sum1 += __shfl_xor_sync(0xffffffffu, sum1, 2);
            l0 = l0 * a0 + sum0;
            l1 = l1 * a1 + sum1;
            m0 = nm0;
            m1 = nm1;

            #pragma unroll
            for (int nt = 0; nt < 16; nt++) {
                oacc[nt][0] *= a0;
                oacc[nt][1] *= a0;
                oacc[nt][2] *= a1;
                oacc[nt][3] *= a1;
            }

            const int sub = lane >> 3, r = lane & 7;
            #pragma unroll
            for (int kc2 = 0; kc2 < 4; kc2++) {
                const int n0 = 2 * kc2, n1 = n0 + 1;
                uint32_t pah[4], pal[4];
                {
                    float p00 = sacc[n0][0], p01 = sacc[n0][1];
                    float p02 = sacc[n0][2], p03 = sacc[n0][3];
                    float p10 = sacc[n1][0], p11 = sacc[n1][1];
                    float p12 = sacc[n1][2], p13 = sacc[n1][3];
                    uint32_t h0 = pack_bf2(p00, p01), h1 = pack_bf2(p02, p03);
                    uint32_t h2 = pack_bf2(p10, p11), h3 = pack_bf2(p12, p13);
                    pah[0] = h0; pah[1] = h1; pah[2] = h2; pah[3] = h3;
                    __nv_bfloat162 t0 = *(__nv_bfloat162*)&h0;
                    __nv_bfloat162 t1 = *(__nv_bfloat162*)&h1;
                    __nv_bfloat162 t2 = *(__nv_bfloat162*)&h2;
                    __nv_bfloat162 t3 = *(__nv_bfloat162*)&h3;
                    pal[0] = pack_bf2(p00 - __bfloat162float(t0.x),
                                      p01 - __bfloat162float(t0.y));
                    pal[1] = pack_bf2(p02 - __bfloat162float(t1.x),
                                      p03 - __bfloat162float(t1.y));
                    pal[2] = pack_bf2(p10 - __bfloat162float(t2.x),
                                      p11 - __bfloat162float(t2.y));
                    pal[3] = pack_bf2(p12 - __bfloat162float(t3.x),
                                      p13 - __bfloat162float(t3.y));
                }
                #pragma unroll
                for (int ntb = 0; ntb < 8; ntb++) {
                    uint32_t vh4[4], vl4[4];
                    int row = kc2 * 16 + ((sub & 1) << 3) + r;
                    int col = ntb * 16 + ((sub >> 1) << 3);
                    uint32_t a = smem_u32(bVh + row * KST + col);
                    ldsm4t(vh4, a);
                    ldsm4t(vl4, a + KV_ELEMS * 2);
                    mma16816(oacc[2 * ntb], pah, vh4[0], vh4[1]);
                    mma16816(oacc[2 * ntb], pah, vl4[0], vl4[1]);
                    mma16816(oacc[2 * ntb], pal, vh4[0], vh4[1]);
                    mma16816(oacc[2 * ntb + 1], pah, vh4[2], vh4[3]);
                    mma16816(oacc[2 * ntb + 1], pah, vl4[2], vl4[3]);
                    mma16816(oacc[2 * ntb + 1], pal, vh4[2], vh4[3]);
                }
            }
        }
        __syncthreads();
    }

    float inv0 = 1.f / l0, inv1 = 1.f / l1;
    size_t row0 = qoff + (size_t)(w * 16 + (lane >> 2)) * D_MODEL;
    size_t row1 = row0 + (size_t)8 * D_MODEL;
    #pragma unroll
    for (int nt = 0; nt < 16; nt++) {
        int c = nt * 8 + (lane & 3) * 2;
        float v00 = oacc[nt][0] * inv0, v01 = oacc[nt][1] * inv0;
        float v10 = oacc[nt][2] * inv1, v11 = oacc[nt][3] * inv1;
        __nv_bfloat16 h00 = __float2bfloat16(v00);
        __nv_bfloat16 h01 = __float2bfloat16(v01);
        __nv_bfloat16 h10 = __float2bfloat16(v10);
        __nv_bfloat16 h11 = __float2bfloat16(v11);
        *(__nv_bfloat162*)(Oh + row0 + c) = __nv_bfloat162(h00, h01);
        *(__nv_bfloat162*)(Oh + row1 + c) = __nv_bfloat162(h10, h11);
        *(__nv_bfloat162*)(Ol + row0 + c) = __nv_bfloat162(
            __float2bfloat16(v00 - __bfloat162float(h00)),
            __float2bfloat16(v01 - __bfloat162float(h01)));
        *(__nv_bfloat162*)(Ol + row1 + c) = __nv_bfloat162(
            __float2bfloat16(v10 - __bfloat162float(h10)),
            __float2bfloat16(v11 - __bfloat162float(h11)));
    }
}

// ---------------------------------------------------------------------------
extern "C" void kernel_launch(void* const* d_in, const int* in_sizes, int n_in,
                              void* d_out, int out_size)
{
    const float* x  = (const float*)d_in[0];
    const float* Wq = (const float*)d_in[1];
    const float* bq = (const float*)d_in[2];
    const float* Wk = (const float*)d_in[3];
    const float* bk = (const float*)d_in[4];
    const float* Wv = (const float*)d_in[5];
    const float* bv = (const float*)d_in[6];
    const float* Wo = (const float*)d_in[7];
    const float* bo = (const float*)d_in[8];
    float* out = (float*)d_out;

    __nv_bfloat16 *xh, *xl, *wqh, *wql, *wkh, *wkl, *wvh, *wvl, *woh, *wol;
    __nv_bfloat16 *qh, *ql, *kh, *kl, *vh, *vl, *ah, *al;
    cudaGetSymbolAddress((void**)&xh, g_xh);
    cudaGetSymbolAddress((void**)&xl, g_xl);
    cudaGetSymbolAddress((void**)&wqh, g_wqh);
    cudaGetSymbolAddress((void**)&wql, g_wql);
    cudaGetSymbolAddress((void**)&wkh, g_wkh);
    cudaGetSymbolAddress((void**)&wkl, g_wkl);
    cudaGetSymbolAddress((void**)&wvh, g_wvh);
    cudaGetSymbolAddress((void**)&wvl, g_wvl);
    cudaGetSymbolAddress((void**)&woh, g_woh);
    cudaGetSymbolAddress((void**)&wol, g_wol);
    cudaGetSymbolAddress((void**)&qh, g_qh);
    cudaGetSymbolAddress((void**)&ql, g_ql);
    cudaGetSymbolAddress((void**)&kh, g_kh);
    cudaGetSymbolAddress((void**)&kl, g_kl);
    cudaGetSymbolAddress((void**)&vh, g_vh);
    cudaGetSymbolAddress((void**)&vl, g_vl);
    cudaGetSymbolAddress((void**)&ah, g_ah);
    cudaGetSymbolAddress((void**)&al, g_al);

    cudaFuncSetAttribute(gemm_qkv,
                         cudaFuncAttributeMaxDynamicSharedMemorySize,
                         GEMM_SMEM_BYTES);
    cudaFuncSetAttribute(gemm_out,
                         cudaFuncAttributeMaxDynamicSharedMemorySize,
                         GEMM_SMEM_BYTES);
    cudaFuncSetAttribute(attn_mma,
                         cudaFuncAttributeMaxDynamicSharedMemorySize,
                         ATT_SMEM_BYTES);

    // split inputs into hi/lo bf16
    {
        int n;
        n = MROWS * D_MODEL;   split_f32<<<n / 4 / 256, 256>>>(x,  xh,  xl,  n);
        n = D_MODEL * D_MODEL; split_f32<<<n / 4 / 256, 256>>>(Wq, wqh, wql, n);
        n = D_MODEL * D_KV;    split_f32<<<n / 4 / 256, 256>>>(Wk, wkh, wkl, n);
        n = D_MODEL * D_KV;    split_f32<<<n / 4 / 256, 256>>>(Wv, wvh, wvl, n);
        n = D_MODEL * D_MODEL; split_f32<<<n / 4 / 256, 256>>>(Wo, woh, wol, n);
    }

    // fused QKV projections -> bf16 hi/lo
    gemm_qkv<<<dim3(24, MROWS / BM), 256, GEMM_SMEM_BYTES>>>(
        xh, xl, wqh, wql, wkh, wkl, wvh, wvl, bq, bk, bv,
        qh, ql, kh, kl, vh, vl);

    // fused causal GQA attention on tensor cores
    attn_mma<<<dim3(TSEQ / 128, HQ, BATCH), 256, ATT_SMEM_BYTES>>>(
        qh, ql, kh, kl, vh, vl, ah, al);

    // output projection -> fp32 out
    gemm_out<<<dim3(D_MODEL / BN, MROWS / BM), 256, GEMM_SMEM_BYTES>>>(
        ah, al, woh, wol, bo, out);
}

// round 6
// speedup vs baseline: 5.2456x; 1.0244x over previous
#include <cuda_runtime.h>
#include <cuda_bf16.h>
#include <cstdint>

#define D_MODEL 2048
#define D_KV    512
#define HQ      16
#define DH      128
#define BATCH   2
#define TSEQ    2048
#define MROWS   (BATCH * TSEQ)   // 4096

// ---------------- scratch (__device__ globals; no allocation allowed) -------
__device__ __nv_bfloat16 g_xh[MROWS * D_MODEL];
__device__ __nv_bfloat16 g_xl[MROWS * D_MODEL];
__device__ __nv_bfloat16 g_wqh[D_MODEL * D_MODEL];
__device__ __nv_bfloat16 g_wql[D_MODEL * D_MODEL];
__device__ __nv_bfloat16 g_wkh[D_MODEL * D_KV];
__device__ __nv_bfloat16 g_wkl[D_MODEL * D_KV];
__device__ __nv_bfloat16 g_wvh[D_MODEL * D_KV];
__device__ __nv_bfloat16 g_wvl[D_MODEL * D_KV];
__device__ __nv_bfloat16 g_woh[D_MODEL * D_MODEL];
__device__ __nv_bfloat16 g_wol[D_MODEL * D_MODEL];

__device__ __nv_bfloat16 g_qh[MROWS * D_MODEL];
__device__ __nv_bfloat16 g_ql[MROWS * D_MODEL];
__device__ __nv_bfloat16 g_kh[MROWS * D_KV];
__device__ __nv_bfloat16 g_kl[MROWS * D_KV];
__device__ __nv_bfloat16 g_vh[MROWS * D_KV];
__device__ __nv_bfloat16 g_vl[MROWS * D_KV];
__device__ __nv_bfloat16 g_ah[MROWS * D_MODEL];
__device__ __nv_bfloat16 g_al[MROWS * D_MODEL];

// ---------------------------------------------------------------------------
__global__ void __launch_bounds__(256) split_f32(
    const float* __restrict__ s, __nv_bfloat16* __restrict__ hi,
    __nv_bfloat16* __restrict__ lo, int n)
{
    int i = (blockIdx.x * blockDim.x + threadIdx.x) * 4;
    if (i >= n) return;
    float4 v = *(const float4*)(s + i);
    float f[4] = {v.x, v.y, v.z, v.w};
    __nv_bfloat16 h[4], l[4];
    #pragma unroll
    for (int j = 0; j < 4; j++) {
        h[j] = __float2bfloat16(f[j]);
        l[j] = __float2bfloat16(f[j] - __bfloat162float(h[j]));
    }
    ((__nv_bfloat162*)(hi + i))[0] = __nv_bfloat162(h[0], h[1]);
    ((__nv_bfloat162*)(hi + i))[1] = __nv_bfloat162(h[2], h[3]);
    ((__nv_bfloat162*)(lo + i))[0] = __nv_bfloat162(l[0], l[1]);
    ((__nv_bfloat162*)(lo + i))[1] = __nv_bfloat162(l[2], l[3]);
}

// ---------------------------------------------------------------------------
// helpers
// ---------------------------------------------------------------------------
__device__ __forceinline__ uint32_t smem_u32(const void* p) {
    return (uint32_t)__cvta_generic_to_shared(p);
}
__device__ __forceinline__ void cp16(uint32_t d, const void* s) {
    asm volatile("cp.async.cg.shared.global [%0], [%1], 16;\n" :: "r"(d), "l"(s));
}
__device__ __forceinline__ void ldsm4(uint32_t* r, uint32_t a) {
    asm volatile("ldmatrix.sync.aligned.m8n8.x4.shared.b16 {%0,%1,%2,%3}, [%4];"
        : "=r"(r[0]), "=r"(r[1]), "=r"(r[2]), "=r"(r[3]) : "r"(a));
}
__device__ __forceinline__ void ldsm4t(uint32_t* r, uint32_t a) {
    asm volatile("ldmatrix.sync.aligned.m8n8.x4.trans.shared.b16 {%0,%1,%2,%3}, [%4];"
        : "=r"(r[0]), "=r"(r[1]), "=r"(r[2]), "=r"(r[3]) : "r"(a));
}
__device__ __forceinline__ void mma16816(float* d, const uint32_t* a,
                                         uint32_t b0, uint32_t b1) {
    asm volatile(
        "mma.sync.aligned.m16n8k16.row.col.f32.bf16.bf16.f32 "
        "{%0,%1,%2,%3}, {%4,%5,%6,%7}, {%8,%9}, {%0,%1,%2,%3};"
        : "+f"(d[0]), "+f"(d[1]), "+f"(d[2]), "+f"(d[3])
        : "r"(a[0]), "r"(a[1]), "r"(a[2]), "r"(a[3]), "r"(b0), "r"(b1));
}
__device__ __forceinline__ uint32_t pack_bf2(float x, float y) {
    __nv_bfloat162 t(__float2bfloat16(x), __float2bfloat16(y));
    return *(uint32_t*)&t;
}

// ---------------------------------------------------------------------------
// GEMM core: 2-term bf16 split, 128x128x32 tile, 3-stage cp.async pipeline.
// MMAs issued TERM-OUTER: 16 independent accumulators between dependent
// writes to the same acc (latency hiding for mma.sync).
// ---------------------------------------------------------------------------
#define BM 128
#define BN 128
#define BK 32
#define AST 40
#define BST 136
#define A_TILE (BM * AST)
#define B_TILE (BK * BST)
#define STAGE_ELEMS (2 * A_TILE + 2 * B_TILE)      // 18944
#define GEMM_STAGES 3
#define GEMM_SMEM_BYTES (GEMM_STAGES * STAGE_ELEMS * 2)   // 113664

template<int OUT_MODE>
__device__ __forceinline__ void gemm_core(
    const __nv_bfloat16* __restrict__ Ah, const __nv_bfloat16* __restrict__ Al,
    const __nv_bfloat16* __restrict__ Bh, const __nv_bfloat16* __restrict__ Bl,
    const float* __restrict__ bias, float* __restrict__ C,
    __nv_bfloat16* __restrict__ Ch, __nv_bfloat16* __restrict__ Cl,
    int N, int K, int am0, int bn0, __nv_bfloat16* sm)
{
    const int tid = threadIdx.x;
    const int lane = tid & 31;
    const int wid = tid >> 5;
    const int wr = wid >> 2;
    const int wc = wid & 3;

    float acc[4][4][4];
    #pragma unroll
    for (int mt = 0; mt < 4; mt++)
        #pragma unroll
        for (int nt = 0; nt < 4; nt++)
            #pragma unroll
            for (int e = 0; e < 4; e++) acc[mt][nt][e] = 0.f;

    auto load_stage = [&](int kt, int s) {
        const int k0 = kt * BK;
        __nv_bfloat16* base = sm + s * STAGE_ELEMS;
        #pragma unroll
        for (int i = 0; i < 2; i++) {
            int idx = tid + i * 256;
            int row = idx >> 2, ch = idx & 3;
            uint32_t d = smem_u32(base + row * AST + ch * 8);
            const size_t g = (size_t)(am0 + row) * K + k0 + ch * 8;
            cp16(d, Ah + g);
            cp16(d + A_TILE * 2, Al + g);
        }
        #pragma unroll
        for (int i = 0; i < 2; i++) {
            int idx = tid + i * 256;
            int row = idx >> 4, ch = idx & 15;
            uint32_t d = smem_u32(base + 2 * A_TILE + row * BST + ch * 8);
            const size_t g = (size_t)(k0 + row) * N + bn0 + ch * 8;
            cp16(d, Bh + g);
            cp16(d + B_TILE * 2, Bl + g);
        }
    };

    auto compute_stage = [&](int s) {
        __nv_bfloat16* base = sm + s * STAGE_ELEMS;
        const int sub = lane >> 3, r = lane & 7;
        #pragma unroll
        for (int ks = 0; ks < 2; ks++) {
            uint32_t ah[4][4], al[4][4], bh[2][4], bl[2][4];
            #pragma unroll
            for (int mt = 0; mt < 4; mt++) {
                int row = wr * 64 + mt * 16 + ((sub & 1) << 3) + r;
                int col = ks * 16 + ((sub >> 1) << 3);
                uint32_t a = smem_u32(base + row * AST + col);
                ldsm4(ah[mt], a);
                ldsm4(al[mt], a + A_TILE * 2);
            }
            #pragma unroll
            for (int ng = 0; ng < 2; ng++) {
                int krow = ks * 16 + ((sub & 1) << 3) + r;
                int ncol = wc * 32 + ng * 16 + ((sub >> 1) << 3);
                uint32_t b = smem_u32(base + 2 * A_TILE + krow * BST + ncol);
                ldsm4t(bh[ng], b);
                ldsm4t(bl[ng], b + B_TILE * 2);
            }
            // term-outer: consecutive MMAs hit different accumulators
            #pragma unroll
            for (int t3 = 0; t3 < 3; t3++)
                #pragma unroll
                for (int mt = 0; mt < 4; mt++)
                    #pragma unroll
                    for (int nt = 0; nt < 4; nt++) {
                        int ng = nt >> 1, o = (nt & 1) * 2;
                        const uint32_t* a = (t3 == 2) ? al[mt] : ah[mt];
                        uint32_t b0 = (t3 == 1) ? bl[ng][o] : bh[ng][o];
                        uint32_t b1 = (t3 == 1) ? bl[ng][o + 1] : bh[ng][o + 1];
                        mma16816(acc[mt][nt], a, b0, b1);
                    }
        }
    };

    const int ktot = K / BK;
    load_stage(0, 0);
    asm volatile("cp.async.commit_group;\n");
    load_stage(1, 1);
    asm volatile("cp.async.commit_group;\n");

    int s_comp = 0, s_load = 2;
    for (int kt = 0; kt < ktot; kt++) {
        asm volatile("cp.async.wait_group 1;\n");
        __syncthreads();
        if (kt + 2 < ktot) load_stage(kt + 2, s_load);
        asm volatile("cp.async.commit_group;\n");
        compute_stage(s_comp);
        s_comp = (s_comp == GEMM_STAGES - 1) ? 0 : s_comp + 1;
        s_load = (s_load == GEMM_STAGES - 1) ? 0 : s_load + 1;
    }

    const int rbase = am0 + wr * 64;
    const int cbase = bn0 + wc * 32;
    #pragma unroll
    for (int mt = 0; mt < 4; mt++) {
        int r0 = rbase + mt * 16 + (lane >> 2);
        #pragma unroll
        for (int nt = 0; nt < 4; nt++) {
            int c = cbase + nt * 8 + (lane & 3) * 2;
            float b0 = bias[c], b1 = bias[c + 1];
            float v00 = acc[mt][nt][0] + b0, v01 = acc[mt][nt][1] + b1;
            float v10 = acc[mt][nt][2] + b0, v11 = acc[mt][nt][3] + b1;
            if (OUT_MODE == 0) {
                *(float2*)(C + (size_t)r0 * N + c) = make_float2(v00, v01);
                *(float2*)(C + (size_t)(r0 + 8) * N + c) = make_float2(v10, v11);
            } else {
                __nv_bfloat16 h00 = __float2bfloat16(v00);
                __nv_bfloat16 h01 = __float2bfloat16(v01);
                __nv_bfloat16 h10 = __float2bfloat16(v10);
                __nv_bfloat16 h11 = __float2bfloat16(v11);
                *(__nv_bfloat162*)(Ch + (size_t)r0 * N + c) = __nv_bfloat162(h00, h01);
                *(__nv_bfloat162*)(Ch + (size_t)(r0 + 8) * N + c) = __nv_bfloat162(h10, h11);
                *(__nv_bfloat162*)(Cl + (size_t)r0 * N + c) = __nv_bfloat162(
                    __float2bfloat16(v00 - __bfloat162float(h00)),
                    __float2bfloat16(v01 - __bfloat162float(h01)));
                *(__nv_bfloat162*)(Cl + (size_t)(r0 + 8) * N + c) = __nv_bfloat162(
                    __float2bfloat16(v10 - __bfloat162float(h10)),
                    __float2bfloat16(v11 - __bfloat162float(h11)));
            }
        }
    }
}

__global__ void __launch_bounds__(256, 2) gemm_qkv(
    const __nv_bfloat16* __restrict__ xh, const __nv_bfloat16* __restrict__ xl,
    const __nv_bfloat16* __restrict__ wqh, const __nv_bfloat16* __restrict__ wql,
    const __nv_bfloat16* __restrict__ wkh, const __nv_bfloat16* __restrict__ wkl,
    const __nv_bfloat16* __restrict__ wvh, const __nv_bfloat16* __restrict__ wvl,
    const float* __restrict__ bq, const float* __restrict__ bk,
    const float* __restrict__ bv,
    __nv_bfloat16* __restrict__ qh, __nv_bfloat16* __restrict__ ql,
    __nv_bfloat16* __restrict__ kh, __nv_bfloat16* __restrict__ kl,
    __nv_bfloat16* __restrict__ vh, __nv_bfloat16* __restrict__ vl)
{
    extern __shared__ __nv_bfloat16 sm[];
    const int bx = blockIdx.x;
    const int am0 = blockIdx.y * BM;
    if (bx < 16) {
        gemm_core<1>(xh, xl, wqh, wql, bq, nullptr, qh, ql,
                     D_MODEL, D_MODEL, am0, bx * BN, sm);
    } else if (bx < 20) {
        gemm_core<1>(xh, xl, wkh, wkl, bk, nullptr, kh, kl,
                     D_KV, D_MODEL, am0, (bx - 16) * BN, sm);
    } else {
        gemm_core<1>(xh, xl, wvh, wvl, bv, nullptr, vh, vl,
                     D_KV, D_MODEL, am0, (bx - 20) * BN, sm);
    }
}

__global__ void __launch_bounds__(256, 2) gemm_out(
    const __nv_bfloat16* __restrict__ ah, const __nv_bfloat16* __restrict__ al,
    const __nv_bfloat16* __restrict__ woh, const __nv_bfloat16* __restrict__ wol,
    const float* __restrict__ bo, float* __restrict__ out)
{
    extern __shared__ __nv_bfloat16 sm[];
    gemm_core<0>(ah, al, woh, wol, bo, out, nullptr, nullptr,
                 D_MODEL, D_MODEL, blockIdx.y * BM, blockIdx.x * BN, sm);
}

// ---------------------------------------------------------------------------
// Tensor-core fused causal GQA attention, term-outer MMA ordering.
// ---------------------------------------------------------------------------
#define KST 136
#define Q_ELEMS (128 * KST)
#define KV_ELEMS (64 * KST)
#define ATT_STAGE (4 * KV_ELEMS)
#define ATT_SMEM_BYTES ((2 * Q_ELEMS + 2 * ATT_STAGE) * 2)

__global__ void __launch_bounds__(256) attn_mma(
    const __nv_bfloat16* __restrict__ Qh, const __nv_bfloat16* __restrict__ Ql,
    const __nv_bfloat16* __restrict__ Kh, const __nv_bfloat16* __restrict__ Kl,
    const __nv_bfloat16* __restrict__ Vh, const __nv_bfloat16* __restrict__ Vl,
    __nv_bfloat16* __restrict__ Oh, __nv_bfloat16* __restrict__ Ol)
{
    extern __shared__ __nv_bfloat16 sm[];
    __nv_bfloat16* sQh = sm;
    __nv_bfloat16* sQl = sQh + Q_ELEMS;
    __nv_bfloat16* sKV = sQl + Q_ELEMS;

    const int qb = (int)gridDim.x - 1 - (int)blockIdx.x;
    const int h = blockIdx.y, bb = blockIdx.z;
    const int q0 = qb * 128;
    const int tid = threadIdx.x;
    const int lane = tid & 31;
    const int w = tid >> 5;

    const size_t qoff = (size_t)(bb * TSEQ + q0) * D_MODEL + h * DH;
    const size_t kvoff = (size_t)(bb * TSEQ) * D_KV + (h >> 2) * DH;

    #pragma unroll
    for (int i = 0; i < 8; i++) {
        int idx = tid + i * 256;
        int row = idx >> 4, ch = idx & 15;
        uint32_t d = smem_u32(sQh + row * KST + ch * 8);
        cp16(d, Qh + qoff + (size_t)row * D_MODEL + ch * 8);
        cp16(d + Q_ELEMS * 2, Ql + qoff + (size_t)row * D_MODEL + ch * 8);
    }
    asm volatile("cp.async.commit_group;\n");

    const int ntiles = 2 * qb + 2;

    auto load_kv = [&](int t, int s) {
        __nv_bfloat16* base = sKV + s * ATT_STAGE;
        const size_t goff = kvoff + (size_t)(t * 64) * D_KV;
        #pragma unroll
        for (int i = 0; i < 4; i++) {
            int idx = tid + i * 256;
            int row = idx >> 4, ch = idx & 15;
            uint32_t d = smem_u32(base + row * KST + ch * 8);
            size_t g = goff + (size_t)row * D_KV + ch * 8;
            cp16(d, Kh + g);
            cp16(d + KV_ELEMS * 2, Kl + g);
            cp16(d + 2 * KV_ELEMS * 2, Vh + g);
            cp16(d + 3 * KV_ELEMS * 2, Vl + g);
        }
        asm volatile("cp.async.commit_group;\n");
    };

    load_kv(0, 0);

    float oacc[16][4];
    #pragma unroll
    for (int nt = 0; nt < 16; nt++)
        #pragma unroll
        for (int e = 0; e < 4; e++) oacc[nt][e] = 0.f;
    float m0 = -1e30f, m1 = -1e30f, l0 = 0.f, l1 = 0.f;

    const int r0g = q0 + w * 16 + (lane >> 2);
    const int r1g = r0g + 8;
    const float scl = 0.08838834764831845f;

    for (int t = 0; t < ntiles; t++) {
        if (t + 1 < ntiles) {
            load_kv(t + 1, (t + 1) & 1);
            asm volatile("cp.async.wait_group 1;\n");
        } else {
            asm volatile("cp.async.wait_group 0;\n");
        }
        __syncthreads();

        const int s0 = t * 64;
        const bool warp_active = (s0 <= q0 + w * 16 + 15);
        if (warp_active) {
            __nv_bfloat16* base = sKV + (t & 1) * ATT_STAGE;
            __nv_bfloat16* bKh = base;
            __nv_bfloat16* bVh = base + 2 * KV_ELEMS;

            float sacc[8][4];
            #pragma unroll
            for (int nt = 0; nt < 8; nt++)
                #pragma unroll
                for (int e = 0; e < 4; e++) sacc[nt][e] = 0.f;

            #pragma unroll
            for (int kc = 0; kc < 8; kc++) {
                uint32_t qa_h[4], qa_l[4];
                {
                    int row = w * 16 + (lane & 15);
                    int col = kc * 16 + ((lane >> 4) << 3);
                    uint32_t a = smem_u32(sQh + row * KST + col);
                    ldsm4(qa_h, a);
                    ldsm4(qa_l, a + Q_ELEMS * 2);
                }
                uint32_t kb_h[4][4], kb_l[4][4];
                #pragma unroll
                for (int nb = 0; nb < 4; nb++) {
                    int row = nb * 16 + (lane & 15);
                    int col = kc * 16 + ((lane >> 4) << 3);
                    uint32_t a = smem_u32(bKh + row * KST + col);
                    ldsm4(kb_h[nb], a);
                    ldsm4(kb_l[nb], a + KV_ELEMS * 2);
                }
                // term-outer: 8 independent accs between dependent writes
                #pragma unroll
                for (int t3 = 0; t3 < 3; t3++) {
                    const uint32_t* qa = (t3 == 2) ? qa_l : qa_h;
                    #pragma unroll
                    for (int nb = 0; nb < 4; nb++) {
                        const uint32_t* kb = (t3 == 1) ? kb_l[nb] : kb_h[nb];
                        mma16816(sacc[2 * nb], qa, kb[0], kb[2]);
                        mma16816(sacc[2 * nb + 1], qa, kb[1], kb[3]);
                    }
                }
            }

            const bool need_mask = (s0 + 63 > q0 + w * 16);
            #pragma unroll
            for (int nt = 0; nt < 8; nt++) {
                int cg2 = s0 + nt * 8 + (lane & 3) * 2;
                #pragma unroll
                for (int e = 0; e < 4; e++) sacc[nt][e] *= scl;
                if (need_mask) {
                    if (cg2 > r0g)     sacc[nt][0] = -1e30f;
                    if (cg2 + 1 > r0g) sacc[nt][1] = -1e30f;
                    if (cg2 > r1g)     sacc[nt][2] = -1e30f;
                    if (cg2 + 1 > r1g) sacc[nt][3] = -1e30f;
                }
            }

            float mx0 = -1e30f, mx1 = -1e30f;
            #pragma unroll
            for (int nt = 0; nt < 8; nt++) {
                mx0 = fmaxf(mx0, fmaxf(sacc[nt][0], sacc[nt][1]));
                mx1 = fmaxf(mx1, fmaxf(sacc[nt][2], sacc[nt][3]));
            }
            mx0 = fmaxf(mx0, __shfl_xor_sync(0xffffffffu, mx0, 1));
            mx0 = fmaxf(mx0, __shfl_xor_sync(0xffffffffu, mx0, 2));
            mx1 = fmaxf(mx1, __shfl_xor_sync(0xffffffffu, mx1, 1));
            mx1 = fmaxf(mx1, __shfl_xor_sync(0xffffffffu, mx1, 2));
            float nm0 = fmaxf(m0, mx0), nm1 = fmaxf(m1, mx1);
            float a0 = __expf(m0 - nm0), a1 = __expf(m1 - nm1);

            float sum0 = 0.f, sum1 = 0.f;
            #pragma unroll
            for (int nt = 0; nt < 8; nt++) {
                sacc[nt][0] = __expf(sacc[nt][0] - nm0);
                sacc[nt][1] = __expf(sacc[nt][1] - nm0);
                sacc[nt][2] = __expf(sacc[nt][2] - nm1);
                sacc[nt][3] = __expf(sacc[nt][3] - nm1);
                sum0 += sacc[nt][0] + sacc[nt][1];
                sum1 += sacc[nt][2] + sacc[nt][3];
            }
            sum0 += __shfl_xor_sync(0xffffffffu, sum0, 1);
            sum0 += __shfl_xor_sync(0xffffffffu, sum0, 2);
            sum1 += __shfl_xor_sync(0xffffffffu, sum1, 1);
            sum1 += __shfl_xor_sync(0xffffffffu, sum1, 2);
            l0 = l0 * a0 + sum0;
            l1 = l1 * a1 + sum1;
            m0 = nm0;
            m1 = nm1;

            #pragma unroll
            for (int nt = 0; nt < 16; nt++) {
                oacc[nt][0] *= a0;
                oacc[nt][1] *= a0;
                oacc[nt][2] *= a1;
                oacc[nt][3] *= a1;
            }

            const int sub = lane >> 3, r = lane & 7;
            #pragma unroll
            for (int kc2 = 0; kc2 < 4; kc2++) {
                const int n0 = 2 * kc2, n1 = n0 + 1;
                uint32_t pah[4], pal[4];
                {
                    float p00 = sacc[n0][0], p01 = sacc[n0][1];
                    float p02 = sacc[n0][2], p03 = sacc[n0][3];
                    float p10 = sacc[n1][0], p11 = sacc[n1][1];
                    float p12 = sacc[n1][2], p13 = sacc[n1][3];
                    uint32_t h0 = pack_bf2(p00, p01), h1 = pack_bf2(p02, p03);
                    uint32_t h2 = pack_bf2(p10, p11), h3 = pack_bf2(p12, p13);
                    pah[0] = h0; pah[1] = h1; pah[2] = h2; pah[3] = h3;
                    __nv_bfloat162 t0 = *(__nv_bfloat162*)&h0;
                    __nv_bfloat162 t1 = *(__nv_bfloat162*)&h1;
                    __nv_bfloat162 t2 = *(__nv_bfloat162*)&h2;
                    __nv_bfloat162 t3v = *(__nv_bfloat162*)&h3;
                    pal[0] = pack_bf2(p00 - __bfloat162float(t0.x),
                                      p01 - __bfloat162float(t0.y));
                    pal[1] = pack_bf2(p02 - __bfloat162float(t1.x),
                                      p03 - __bfloat162float(t1.y));
                    pal[2] = pack_bf2(p10 - __bfloat162float(t2.x),
                                      p11 - __bfloat162float(t2.y));
                    pal[3] = pack_bf2(p12 - __bfloat162float(t3v.x),
                                      p13 - __bfloat162float(t3v.y));
                }
                // ntb in pairs: 4 live acc targets, term-outer
                #pragma unroll
                for (int np = 0; np < 4; np++) {
                    const int ntb0 = 2 * np, ntb1 = 2 * np + 1;
                    uint32_t vhA[4], vlA[4], vhB[4], vlB[4];
                    int row = kc2 * 16 + ((sub & 1) << 3) + r;
                    int colA = ntb0 * 16 + ((sub >> 1) << 3);
                    int colB = ntb1 * 16 + ((sub >> 1) << 3);
                    uint32_t aA = smem_u32(bVh + row * KST + colA);
                    uint32_t aB = smem_u32(bVh + row * KST + colB);
                    ldsm4t(vhA, aA);
                    ldsm4t(vlA, aA + KV_ELEMS * 2);
                    ldsm4t(vhB, aB);
                    ldsm4t(vlB, aB + KV_ELEMS * 2);
                    #pragma unroll
                    for (int t3 = 0; t3 < 3; t3++) {
                        const uint32_t* p = (t3 == 2) ? pal : pah;
                        const uint32_t* vA = (t3 == 1) ? vlA : vhA;
                        const uint32_t* vB = (t3 == 1) ? vlB : vhB;
                        mma16816(oacc[2 * ntb0], p, vA[0], vA[1]);
                        mma16816(oacc[2 * ntb0 + 1], p, vA[2], vA[3]);
                        mma16816(oacc[2 * ntb1], p, vB[0], vB[1]);
                        mma16816(oacc[2 * ntb1 + 1], p, vB[2], vB[3]);
                    }
                }
            }
        }
        __syncthreads();
    }

    float inv0 = 1.f / l0, inv1 = 1.f / l1;
    size_t row0 = qoff + (size_t)(w * 16 + (lane >> 2)) * D_MODEL;
    size_t row1 = row0 + (size_t)8 * D_MODEL;
    #pragma unroll
    for (int nt = 0; nt < 16; nt++) {
        int c = nt * 8 + (lane & 3) * 2;
        float v00 = oacc[nt][0] * inv0, v01 = oacc[nt][1] * inv0;
        float v10 = oacc[nt][2] * inv1, v11 = oacc[nt][3] * inv1;
        __nv_bfloat16 h00 = __float2bfloat16(v00);
        __nv_bfloat16 h01 = __float2bfloat16(v01);
        __nv_bfloat16 h10 = __float2bfloat16(v10);
        __nv_bfloat16 h11 = __float2bfloat16(v11);
        *(__nv_bfloat162*)(Oh + row0 + c) = __nv_bfloat162(h00, h01);
        *(__nv_bfloat162*)(Oh + row1 + c) = __nv_bfloat162(h10, h11);
        *(__nv_bfloat162*)(Ol + row0 + c) = __nv_bfloat162(
            __float2bfloat16(v00 - __bfloat162float(h00)),
            __float2bfloat16(v01 - __bfloat162float(h01)));
        *(__nv_bfloat162*)(Ol + row1 + c) = __nv_bfloat162(
            __float2bfloat16(v10 - __bfloat162float(h10)),
            __float2bfloat16(v11 - __bfloat162float(h11)));
    }
}

// ---------------------------------------------------------------------------
extern "C" void kernel_launch(void* const* d_in, const int* in_sizes, int n_in,
                              void* d_out, int out_size)
{
    const float* x  = (const float*)d_in[0];
    const float* Wq = (const float*)d_in[1];
    const float* bq = (const float*)d_in[2];
    const float* Wk = (const float*)d_in[3];
    const float* bk = (const float*)d_in[4];
    const float* Wv = (const float*)d_in[5];
    const float* bv = (const float*)d_in[6];
    const float* Wo = (const float*)d_in[7];
    const float* bo = (const float*)d_in[8];
    float* out = (float*)d_out;

    __nv_bfloat16 *xh, *xl, *wqh, *wql, *wkh, *wkl, *wvh, *wvl, *woh, *wol;
    __nv_bfloat16 *qh, *ql, *kh, *kl, *vh, *vl, *ah, *al;
    cudaGetSymbolAddress((void**)&xh, g_xh);
    cudaGetSymbolAddress((void**)&xl, g_xl);
    cudaGetSymbolAddress((void**)&wqh, g_wqh);
    cudaGetSymbolAddress((void**)&wql, g_wql);
    cudaGetSymbolAddress((void**)&wkh, g_wkh);
    cudaGetSymbolAddress((void**)&wkl, g_wkl);
    cudaGetSymbolAddress((void**)&wvh, g_wvh);
    cudaGetSymbolAddress((void**)&wvl, g_wvl);
    cudaGetSymbolAddress((void**)&woh, g_woh);
    cudaGetSymbolAddress((void**)&wol, g_wol);
    cudaGetSymbolAddress((void**)&qh, g_qh);
    cudaGetSymbolAddress((void**)&ql, g_ql);
    cudaGetSymbolAddress((void**)&kh, g_kh);
    cudaGetSymbolAddress((void**)&kl, g_kl);
    cudaGetSymbolAddress((void**)&vh, g_vh);
    cudaGetSymbolAddress((void**)&vl, g_vl);
    cudaGetSymbolAddress((void**)&ah, g_ah);
    cudaGetSymbolAddress((void**)&al, g_al);

    cudaFuncSetAttribute(gemm_qkv,
                         cudaFuncAttributeMaxDynamicSharedMemorySize,
                         GEMM_SMEM_BYTES);
    cudaFuncSetAttribute(gemm_out,
                         cudaFuncAttributeMaxDynamicSharedMemorySize,
                         GEMM_SMEM_BYTES);
    cudaFuncSetAttribute(attn_mma,
                         cudaFuncAttributeMaxDynamicSharedMemorySize,
                         ATT_SMEM_BYTES);

    // split inputs into hi/lo bf16
    {
        int n;
        n = MROWS * D_MODEL;   split_f32<<<n / 4 / 256, 256>>>(x,  xh,  xl,  n);
        n = D_MODEL * D_MODEL; split_f32<<<n / 4 / 256, 256>>>(Wq, wqh, wql, n);
        n = D_MODEL * D_KV;    split_f32<<<n / 4 / 256, 256>>>(Wk, wkh, wkl, n);
        n = D_MODEL * D_KV;    split_f32<<<n / 4 / 256, 256>>>(Wv, wvh, wvl, n);
        n = D_MODEL * D_MODEL; split_f32<<<n / 4 / 256, 256>>>(Wo, woh, wol, n);
    }

    // fused QKV projections -> bf16 hi/lo
    gemm_qkv<<<dim3(24, MROWS / BM), 256, GEMM_SMEM_BYTES>>>(
        xh, xl, wqh, wql, wkh, wkl, wvh, wvl, bq, bk, bv,
        qh, ql, kh, kl, vh, vl);

    // fused causal GQA attention on tensor cores
    attn_mma<<<dim3(TSEQ / 128, HQ, BATCH), 256, ATT_SMEM_BYTES>>>(
        qh, ql, kh, kl, vh, vl, ah, al);

    // output projection -> fp32 out
    gemm_out<<<dim3(D_MODEL / BN, MROWS / BM), 256, GEMM_SMEM_BYTES>>>(
        ah, al, woh, wol, bo, out);
}

// round 8
// speedup vs baseline: 5.3047x; 1.0113x over previous
#include <cuda_runtime.h>
#include <cuda_bf16.h>
#include <cstdint>

#define D_MODEL 2048
#define D_KV    512
#define HQ      16
#define DH      128
#define BATCH   2
#define TSEQ    2048
#define MROWS   (BATCH * TSEQ)   // 4096

// ---------------- scratch (__device__ globals; no allocation allowed) -------
__device__ __nv_bfloat16 g_xh[MROWS * D_MODEL];
__device__ __nv_bfloat16 g_xl[MROWS * D_MODEL];
__device__ __nv_bfloat16 g_wqh[D_MODEL * D_MODEL];
__device__ __nv_bfloat16 g_wql[D_MODEL * D_MODEL];
__device__ __nv_bfloat16 g_wkh[D_MODEL * D_KV];
__device__ __nv_bfloat16 g_wkl[D_MODEL * D_KV];
__device__ __nv_bfloat16 g_wvh[D_MODEL * D_KV];
__device__ __nv_bfloat16 g_wvl[D_MODEL * D_KV];
__device__ __nv_bfloat16 g_woh[D_MODEL * D_MODEL];
__device__ __nv_bfloat16 g_wol[D_MODEL * D_MODEL];

__device__ __nv_bfloat16 g_qh[MROWS * D_MODEL];
__device__ __nv_bfloat16 g_ql[MROWS * D_MODEL];
__device__ __nv_bfloat16 g_kh[MROWS * D_KV];
__device__ __nv_bfloat16 g_kl[MROWS * D_KV];
__device__ __nv_bfloat16 g_vh[MROWS * D_KV];
__device__ __nv_bfloat16 g_vl[MROWS * D_KV];
__device__ __nv_bfloat16 g_ah[MROWS * D_MODEL];
__device__ __nv_bfloat16 g_al[MROWS * D_MODEL];

// ---------------------------------------------------------------------------
__global__ void __launch_bounds__(256) split_f32(
    const float* __restrict__ s, __nv_bfloat16* __restrict__ hi,
    __nv_bfloat16* __restrict__ lo, int n)
{
    int i = (blockIdx.x * blockDim.x + threadIdx.x) * 4;
    if (i >= n) return;
    float4 v = *(const float4*)(s + i);
    float f[4] = {v.x, v.y, v.z, v.w};
    __nv_bfloat16 h[4], l[4];
    #pragma unroll
    for (int j = 0; j < 4; j++) {
        h[j] = __float2bfloat16(f[j]);
        l[j] = __float2bfloat16(f[j] - __bfloat162float(h[j]));
    }
    ((__nv_bfloat162*)(hi + i))[0] = __nv_bfloat162(h[0], h[1]);
    ((__nv_bfloat162*)(hi + i))[1] = __nv_bfloat162(h[2], h[3]);
    ((__nv_bfloat162*)(lo + i))[0] = __nv_bfloat162(l[0], l[1]);
    ((__nv_bfloat162*)(lo + i))[1] = __nv_bfloat162(l[2], l[3]);
}

// ---------------------------------------------------------------------------
// helpers
// ---------------------------------------------------------------------------
__device__ __forceinline__ uint32_t smem_u32(const void* p) {
    return (uint32_t)__cvta_generic_to_shared(p);
}
__device__ __forceinline__ void cp16(uint32_t d, const void* s) {
    asm volatile("cp.async.cg.shared.global [%0], [%1], 16;\n" :: "r"(d), "l"(s));
}
__device__ __forceinline__ void ldsm4(uint32_t* r, uint32_t a) {
    asm volatile("ldmatrix.sync.aligned.m8n8.x4.shared.b16 {%0,%1,%2,%3}, [%4];"
        : "=r"(r[0]), "=r"(r[1]), "=r"(r[2]), "=r"(r[3]) : "r"(a));
}
__device__ __forceinline__ void ldsm4t(uint32_t* r, uint32_t a) {
    asm volatile("ldmatrix.sync.aligned.m8n8.x4.trans.shared.b16 {%0,%1,%2,%3}, [%4];"
        : "=r"(r[0]), "=r"(r[1]), "=r"(r[2]), "=r"(r[3]) : "r"(a));
}
__device__ __forceinline__ void mma16816(float* d, const uint32_t* a,
                                         uint32_t b0, uint32_t b1) {
    asm volatile(
        "mma.sync.aligned.m16n8k16.row.col.f32.bf16.bf16.f32 "
        "{%0,%1,%2,%3}, {%4,%5,%6,%7}, {%8,%9}, {%0,%1,%2,%3};"
        : "+f"(d[0]), "+f"(d[1]), "+f"(d[2]), "+f"(d[3])
        : "r"(a[0]), "r"(a[1]), "r"(a[2]), "r"(a[3]), "r"(b0), "r"(b1));
}
__device__ __forceinline__ uint32_t pack_bf2(float x, float y) {
    __nv_bfloat162 t(__float2bfloat16(x), __float2bfloat16(y));
    return *(uint32_t*)&t;
}

// ---------------------------------------------------------------------------
// GEMM core (unchanged): 2-term bf16 split, 128x128x32 tile,
// 3-stage cp.async pipeline, term-outer MMA ordering.
// ---------------------------------------------------------------------------
#define BM 128
#define BN 128
#define BK 32
#define AST 40
#define BST 136
#define A_TILE (BM * AST)
#define B_TILE (BK * BST)
#define STAGE_ELEMS (2 * A_TILE + 2 * B_TILE)
#define GEMM_STAGES 3
#define GEMM_SMEM_BYTES (GEMM_STAGES * STAGE_ELEMS * 2)

template<int OUT_MODE>
__device__ __forceinline__ void gemm_core(
    const __nv_bfloat16* __restrict__ Ah, const __nv_bfloat16* __restrict__ Al,
    const __nv_bfloat16* __restrict__ Bh, const __nv_bfloat16* __restrict__ Bl,
    const float* __restrict__ bias, float* __restrict__ C,
    __nv_bfloat16* __restrict__ Ch, __nv_bfloat16* __restrict__ Cl,
    int N, int K, int am0, int bn0, __nv_bfloat16* sm)
{
    const int tid = threadIdx.x;
    const int lane = tid & 31;
    const int wid = tid >> 5;
    const int wr = wid >> 2;
    const int wc = wid & 3;

    float acc[4][4][4];
    #pragma unroll
    for (int mt = 0; mt < 4; mt++)
        #pragma unroll
        for (int nt = 0; nt < 4; nt++)
            #pragma unroll
            for (int e = 0; e < 4; e++) acc[mt][nt][e] = 0.f;

    auto load_stage = [&](int kt, int s) {
        const int k0 = kt * BK;
        __nv_bfloat16* base = sm + s * STAGE_ELEMS;
        #pragma unroll
        for (int i = 0; i < 2; i++) {
            int idx = tid + i * 256;
            int row = idx >> 2, ch = idx & 3;
            uint32_t d = smem_u32(base + row * AST + ch * 8);
            const size_t g = (size_t)(am0 + row) * K + k0 + ch * 8;
            cp16(d, Ah + g);
            cp16(d + A_TILE * 2, Al + g);
        }
        #pragma unroll
        for (int i = 0; i < 2; i++) {
            int idx = tid + i * 256;
            int row = idx >> 4, ch = idx & 15;
            uint32_t d = smem_u32(base + 2 * A_TILE + row * BST + ch * 8);
            const size_t g = (size_t)(k0 + row) * N + bn0 + ch * 8;
            cp16(d, Bh + g);
            cp16(d + B_TILE * 2, Bl + g);
        }
    };

    auto compute_stage = [&](int s) {
        __nv_bfloat16* base = sm + s * STAGE_ELEMS;
        const int sub = lane >> 3, r = lane & 7;
        #pragma unroll
        for (int ks = 0; ks < 2; ks++) {
            uint32_t ah[4][4], al[4][4], bh[2][4], bl[2][4];
            #pragma unroll
            for (int mt = 0; mt < 4; mt++) {
                int row = wr * 64 + mt * 16 + ((sub & 1) << 3) + r;
                int col = ks * 16 + ((sub >> 1) << 3);
                uint32_t a = smem_u32(base + row * AST + col);
                ldsm4(ah[mt], a);
                ldsm4(al[mt], a + A_TILE * 2);
            }
            #pragma unroll
            for (int ng = 0; ng < 2; ng++) {
                int krow = ks * 16 + ((sub & 1) << 3) + r;
                int ncol = wc * 32 + ng * 16 + ((sub >> 1) << 3);
                uint32_t b = smem_u32(base + 2 * A_TILE + krow * BST + ncol);
                ldsm4t(bh[ng], b);
                ldsm4t(bl[ng], b + B_TILE * 2);
            }
            #pragma unroll
            for (int t3 = 0; t3 < 3; t3++)
                #pragma unroll
                for (int mt = 0; mt < 4; mt++)
                    #pragma unroll
                    for (int nt = 0; nt < 4; nt++) {
                        int ng = nt >> 1, o = (nt & 1) * 2;
                        const uint32_t* a = (t3 == 2) ? al[mt] : ah[mt];
                        uint32_t b0 = (t3 == 1) ? bl[ng][o] : bh[ng][o];
                        uint32_t b1 = (t3 == 1) ? bl[ng][o + 1] : bh[ng][o + 1];
                        mma16816(acc[mt][nt], a, b0, b1);
                    }
        }
    };

    const int ktot = K / BK;
    load_stage(0, 0);
    asm volatile("cp.async.commit_group;\n");
    load_stage(1, 1);
    asm volatile("cp.async.commit_group;\n");

    int s_comp = 0, s_load = 2;
    for (int kt = 0; kt < ktot; kt++) {
        asm volatile("cp.async.wait_group 1;\n");
        __syncthreads();
        if (kt + 2 < ktot) load_stage(kt + 2, s_load);
        asm volatile("cp.async.commit_group;\n");
        compute_stage(s_comp);
        s_comp = (s_comp == GEMM_STAGES - 1) ? 0 : s_comp + 1;
        s_load = (s_load == GEMM_STAGES - 1) ? 0 : s_load + 1;
    }

    const int rbase = am0 + wr * 64;
    const int cbase = bn0 + wc * 32;
    #pragma unroll
    for (int mt = 0; mt < 4; mt++) {
        int r0 = rbase + mt * 16 + (lane >> 2);
        #pragma unroll
        for (int nt = 0; nt < 4; nt++) {
            int c = cbase + nt * 8 + (lane & 3) * 2;
            float b0 = bias[c], b1 = bias[c + 1];
            float v00 = acc[mt][nt][0] + b0, v01 = acc[mt][nt][1] + b1;
            float v10 = acc[mt][nt][2] + b0, v11 = acc[mt][nt][3] + b1;
            if (OUT_MODE == 0) {
                *(float2*)(C + (size_t)r0 * N + c) = make_float2(v00, v01);
                *(float2*)(C + (size_t)(r0 + 8) * N + c) = make_float2(v10, v11);
            } else {
                __nv_bfloat16 h00 = __float2bfloat16(v00);
                __nv_bfloat16 h01 = __float2bfloat16(v01);
                __nv_bfloat16 h10 = __float2bfloat16(v10);
                __nv_bfloat16 h11 = __float2bfloat16(v11);
                *(__nv_bfloat162*)(Ch + (size_t)r0 * N + c) = __nv_bfloat162(h00, h01);
                *(__nv_bfloat162*)(Ch + (size_t)(r0 + 8) * N + c) = __nv_bfloat162(h10, h11);
                *(__nv_bfloat162*)(Cl + (size_t)r0 * N + c) = __nv_bfloat162(
                    __float2bfloat16(v00 - __bfloat162float(h00)),
                    __float2bfloat16(v01 - __bfloat162float(h01)));
                *(__nv_bfloat162*)(Cl + (size_t)(r0 + 8) * N + c) = __nv_bfloat162(
                    __float2bfloat16(v10 - __bfloat162float(h10)),
                    __float2bfloat16(v11 - __bfloat162float(h11)));
            }
        }
    }
}

__global__ void __launch_bounds__(256, 2) gemm_qkv(
    const __nv_bfloat16* __restrict__ xh, const __nv_bfloat16* __restrict__ xl,
    const __nv_bfloat16* __restrict__ wqh, const __nv_bfloat16* __restrict__ wql,
    const __nv_bfloat16* __restrict__ wkh, const __nv_bfloat16* __restrict__ wkl,
    const __nv_bfloat16* __restrict__ wvh, const __nv_bfloat16* __restrict__ wvl,
    const float* __restrict__ bq, const float* __restrict__ bk,
    const float* __restrict__ bv,
    __nv_bfloat16* __restrict__ qh, __nv_bfloat16* __restrict__ ql,
    __nv_bfloat16* __restrict__ kh, __nv_bfloat16* __restrict__ kl,
    __nv_bfloat16* __restrict__ vh, __nv_bfloat16* __restrict__ vl)
{
    extern __shared__ __nv_bfloat16 sm[];
    const int bx = blockIdx.x;
    const int am0 = blockIdx.y * BM;
    if (bx < 16) {
        gemm_core<1>(xh, xl, wqh, wql, bq, nullptr, qh, ql,
                     D_MODEL, D_MODEL, am0, bx * BN, sm);
    } else if (bx < 20) {
        gemm_core<1>(xh, xl, wkh, wkl, bk, nullptr, kh, kl,
                     D_KV, D_MODEL, am0, (bx - 16) * BN, sm);
    } else {
        gemm_core<1>(xh, xl, wvh, wvl, bv, nullptr, vh, vl,
                     D_KV, D_MODEL, am0, (bx - 20) * BN, sm);
    }
}

__global__ void __launch_bounds__(256, 2) gemm_out(
    const __nv_bfloat16* __restrict__ ah, const __nv_bfloat16* __restrict__ al,
    const __nv_bfloat16* __restrict__ woh, const __nv_bfloat16* __restrict__ wol,
    const float* __restrict__ bo, float* __restrict__ out)
{
    extern __shared__ __nv_bfloat16 sm[];
    gemm_core<0>(ah, al, woh, wol, bo, out, nullptr, nullptr,
                 D_MODEL, D_MODEL, blockIdx.y * BM, blockIdx.x * BN, sm);
}

// ---------------------------------------------------------------------------
// Fused causal GQA attention: Br=64 (4 warps), Bc=32, 128 threads,
// 2 CTAs/SM (smem 104448 B) so softmax of one CTA overlaps MMAs of the other.
// ---------------------------------------------------------------------------
#define KST 136
#define Q_ELEMS (64 * KST)            // 8704
#define KV_ELEMS (32 * KST)           // 4352
#define ATT_STAGE (4 * KV_ELEMS)      // Kh,Kl,Vh,Vl
#define ATT_SMEM_BYTES ((2 * Q_ELEMS + 2 * ATT_STAGE) * 2)   // 104448

__global__ void __launch_bounds__(128, 2) attn_mma(
    const __nv_bfloat16* __restrict__ Qh, const __nv_bfloat16* __restrict__ Ql,
    const __nv_bfloat16* __restrict__ Kh, const __nv_bfloat16* __restrict__ Kl,
    const __nv_bfloat16* __restrict__ Vh, const __nv_bfloat16* __restrict__ Vl,
    __nv_bfloat16* __restrict__ Oh, __nv_bfloat16* __restrict__ Ol)
{
    extern __shared__ __nv_bfloat16 sm[];
    __nv_bfloat16* sQh = sm;
    __nv_bfloat16* sQl = sQh + Q_ELEMS;
    __nv_bfloat16* sKV = sQl + Q_ELEMS;

    const int qb = (int)gridDim.x - 1 - (int)blockIdx.x;   // heavy blocks first
    const int h = blockIdx.y, bb = blockIdx.z;
    const int q0 = qb * 64;
    const int tid = threadIdx.x;
    const int lane = tid & 31;
    const int w = tid >> 5;             // 0..3

    const size_t qoff = (size_t)(bb * TSEQ + q0) * D_MODEL + h * DH;
    const size_t kvoff = (size_t)(bb * TSEQ) * D_KV + (h >> 2) * DH;

    // ---- load Q (64 rows x 128 cols = 1024 16B chunks, hi/lo) ----
    #pragma unroll
    for (int i = 0; i < 8; i++) {
        int idx = tid + i * 128;
        int row = idx >> 4, ch = idx & 15;
        uint32_t d = smem_u32(sQh + row * KST + ch * 8);
        cp16(d, Qh + qoff + (size_t)row * D_MODEL + ch * 8);
        cp16(d + Q_ELEMS * 2, Ql + qoff + (size_t)row * D_MODEL + ch * 8);
    }
    asm volatile("cp.async.commit_group;\n");

    const int ntiles = 2 * qb + 2;                   // (q0+64)/32

    auto load_kv = [&](int t, int s) {
        __nv_bfloat16* base = sKV + s * ATT_STAGE;
        const size_t goff = kvoff + (size_t)(t * 32) * D_KV;
        #pragma unroll
        for (int i = 0; i < 4; i++) {
            int idx = tid + i * 128;                 // 512 chunks (32 rows x 16)
            int row = idx >> 4, ch = idx & 15;
            uint32_t d = smem_u32(base + row * KST + ch * 8);
            size_t g = goff + (size_t)row * D_KV + ch * 8;
            cp16(d, Kh + g);
            cp16(d + KV_ELEMS * 2, Kl + g);
            cp16(d + 2 * KV_ELEMS * 2, Vh + g);
            cp16(d + 3 * KV_ELEMS * 2, Vl + g);
        }
        asm volatile("cp.async.commit_group;\n");
    };

    load_kv(0, 0);

    float oacc[16][4];
    #pragma unroll
    for (int nt = 0; nt < 16; nt++)
        #pragma unroll
        for (int e = 0; e < 4; e++) oacc[nt][e] = 0.f;
    float m0 = -1e30f, m1 = -1e30f, l0 = 0.f, l1 = 0.f;

    const int r0g = q0 + w * 16 + (lane >> 2);
    const int r1g = r0g + 8;
    const float scl = 0.08838834764831845f;

    for (int t = 0; t < ntiles; t++) {
        if (t + 1 < ntiles) {
            load_kv(t + 1, (t + 1) & 1);
            asm volatile("cp.async.wait_group 1;\n");
        } else {
            asm volatile("cp.async.wait_group 0;\n");
        }
        __syncthreads();

        const int s0 = t * 32;
        const bool warp_active = (s0 <= q0 + w * 16 + 15);
        if (warp_active) {
            __nv_bfloat16* base = sKV + (t & 1) * ATT_STAGE;
            __nv_bfloat16* bKh = base;
            __nv_bfloat16* bVh = base + 2 * KV_ELEMS;

            // ---- S = Q K^T (per warp 16x32 -> sacc[4][4]) ----
            float sacc[4][4];
            #pragma unroll
            for (int nt = 0; nt < 4; nt++)
                #pragma unroll
                for (int e = 0; e < 4; e++) sacc[nt][e] = 0.f;

            #pragma unroll
            for (int kc = 0; kc < 8; kc++) {
                uint32_t qa_h[4], qa_l[4];
                {
                    int row = w * 16 + (lane & 15);
                    int col = kc * 16 + ((lane >> 4) << 3);
                    uint32_t a = smem_u32(sQh + row * KST + col);
                    ldsm4(qa_h, a);
                    ldsm4(qa_l, a + Q_ELEMS * 2);
                }
                uint32_t kb_h[2][4], kb_l[2][4];
                #pragma unroll
                for (int nb = 0; nb < 2; nb++) {
                    int row = nb * 16 + (lane & 15);
                    int col = kc * 16 + ((lane >> 4) << 3);
                    uint32_t a = smem_u32(bKh + row * KST + col);
                    ldsm4(kb_h[nb], a);
                    ldsm4(kb_l[nb], a + KV_ELEMS * 2);
                }
                #pragma unroll
                for (int t3 = 0; t3 < 3; t3++) {
                    const uint32_t* qa = (t3 == 2) ? qa_l : qa_h;
                    #pragma unroll
                    for (int nb = 0; nb < 2; nb++) {
                        const uint32_t* kb = (t3 == 1) ? kb_l[nb] : kb_h[nb];
                        mma16816(sacc[2 * nb], qa, kb[0], kb[2]);
                        mma16816(sacc[2 * nb + 1], qa, kb[1], kb[3]);
                    }
                }
            }

            // ---- scale + causal mask ----
            const bool need_mask = (s0 + 31 > q0 + w * 16);
            #pragma unroll
            for (int nt = 0; nt < 4; nt++) {
                int cg2 = s0 + nt * 8 + (lane & 3) * 2;
                #pragma unroll
                for (int e = 0; e < 4; e++) sacc[nt][e] *= scl;
                if (need_mask) {
                    if (cg2 > r0g)     sacc[nt][0] = -1e30f;
                    if (cg2 + 1 > r0g) sacc[nt][1] = -1e30f;
                    if (cg2 > r1g)     sacc[nt][2] = -1e30f;
                    if (cg2 + 1 > r1g) sacc[nt][3] = -1e30f;
                }
            }

            // ---- online softmax (registers) ----
            float mx0 = -1e30f, mx1 = -1e30f;
            #pragma unroll
            for (int nt = 0; nt < 4; nt++) {
                mx0 = fmaxf(mx0, fmaxf(sacc[nt][0], sacc[nt][1]));
                mx1 = fmaxf(mx1, fmaxf(sacc[nt][2], sacc[nt][3]));
            }
            mx0 = fmaxf(mx0, __shfl_xor_sync(0xffffffffu, mx0, 1));
            mx0 = fmaxf(mx0, __shfl_xor_sync(0xffffffffu, mx0, 2));
            mx1 = fmaxf(mx1, __shfl_xor_sync(0xffffffffu, mx1, 1));
            mx1 = fmaxf(mx1, __shfl_xor_sync(0xffffffffu, mx1, 2));
            float nm0 = fmaxf(m0, mx0), nm1 = fmaxf(m1, mx1);
            float a0 = __expf(m0 - nm0), a1 = __expf(m1 - nm1);

            float sum0 = 0.f, sum1 = 0.f;
            #pragma unroll
            for (int nt = 0; nt < 4; nt++) {
                sacc[nt][0] = __expf(sacc[nt][0] - nm0);
                sacc[nt][1] = __expf(sacc[nt][1] - nm0);
                sacc[nt][2] = __expf(sacc[nt][2] - nm1);
                sacc[nt][3] = __expf(sacc[nt][3] - nm1);
                sum0 += sacc[nt][0] + sacc[nt][1];
                sum1 += sacc[nt][2] + sacc[nt][3];
            }
            sum0 += __shfl_xor_sync(0xffffffffu, sum0, 1);
            sum0 += __shfl_xor_sync(0xffffffffu, sum0, 2);
            sum1 += __shfl_xor_sync(0xffffffffu, sum1, 1);
            sum1 += __shfl_xor_sync(0xffffffffu, sum1, 2);
            l0 = l0 * a0 + sum0;
            l1 = l1 * a1 + sum1;
            m0 = nm0;
            m1 = nm1;

            #pragma unroll
            for (int nt = 0; nt < 16; nt++) {
                oacc[nt][0] *= a0;
                oacc[nt][1] *= a0;
                oacc[nt][2] *= a1;
                oacc[nt][3] *= a1;
            }

            // ---- O += P V (P: 16x32 per warp; V: 32x128) ----
            const int sub = lane >> 3, r = lane & 7;
            #pragma unroll
            for (int kc2 = 0; kc2 < 2; kc2++) {
                const int n0 = 2 * kc2, n1 = n0 + 1;
                uint32_t pah[4], pal[4];
                {
                    float p00 = sacc[n0][0], p01 = sacc[n0][1];
                    float p02 = sacc[n0][2], p03 = sacc[n0][3];
                    float p10 = sacc[n1][0], p11 = sacc[n1][1];
                    float p12 = sacc[n1][2], p13 = sacc[n1][3];
                    uint32_t h0 = pack_bf2(p00, p01), h1 = pack_bf2(p02, p03);
                    uint32_t h2 = pack_bf2(p10, p11), h3 = pack_bf2(p12, p13);
                    pah[0] = h0; pah[1] = h1; pah[2] = h2; pah[3] = h3;
                    __nv_bfloat162 t0 = *(__nv_bfloat162*)&h0;
                    __nv_bfloat162 t1 = *(__nv_bfloat162*)&h1;
                    __nv_bfloat162 t2 = *(__nv_bfloat162*)&h2;
                    __nv_bfloat162 t3v = *(__nv_bfloat162*)&h3;
                    pal[0] = pack_bf2(p00 - __bfloat162float(t0.x),
                                      p01 - __bfloat162float(t0.y));
                    pal[1] = pack_bf2(p02 - __bfloat162float(t1.x),
                                      p03 - __bfloat162float(t1.y));
                    pal[2] = pack_bf2(p10 - __bfloat162float(t2.x),
                                      p11 - __bfloat162float(t2.y));
                    pal[3] = pack_bf2(p12 - __bfloat162float(t3v.x),
                                      p13 - __bfloat162float(t3v.y));
                }
                #pragma unroll
                for (int np = 0; np < 4; np++) {
                    const int ntb0 = 2 * np, ntb1 = 2 * np + 1;
                    uint32_t vhA[4], vlA[4], vhB[4], vlB[4];
                    int row = kc2 * 16 + ((sub & 1) << 3) + r;
                    int colA = ntb0 * 16 + ((sub >> 1) << 3);
                    int colB = ntb1 * 16 + ((sub >> 1) << 3);
                    uint32_t aA = smem_u32(bVh + row * KST + colA);
                    uint32_t aB = smem_u32(bVh + row * KST + colB);
                    ldsm4t(vhA, aA);
                    ldsm4t(vlA, aA + KV_ELEMS * 2);
                    ldsm4t(vhB, aB);
                    ldsm4t(vlB, aB + KV_ELEMS * 2);
                    #pragma unroll
                    for (int t3 = 0; t3 < 3; t3++) {
                        const uint32_t* p = (t3 == 2) ? pal : pah;
                        const uint32_t* vA = (t3 == 1) ? vlA : vhA;
                        const uint32_t* vB = (t3 == 1) ? vlB : vhB;
                        mma16816(oacc[2 * ntb0], p, vA[0], vA[1]);
                        mma16816(oacc[2 * ntb0 + 1], p, vA[2], vA[3]);
                        mma16816(oacc[2 * ntb1], p, vB[0], vB[1]);
                        mma16816(oacc[2 * ntb1 + 1], p, vB[2], vB[3]);
                    }
                }
            }
        }
        __syncthreads();
    }

    // ---- epilogue ----
    float inv0 = 1.f / l0, inv1 = 1.f / l1;
    size_t row0 = qoff + (size_t)(w * 16 + (lane >> 2)) * D_MODEL;
    size_t row1 = row0 + (size_t)8 * D_MODEL;
    #pragma unroll
    for (int nt = 0; nt < 16; nt++) {
        int c = nt * 8 + (lane & 3) * 2;
        float v00 = oacc[nt][0] * inv0, v01 = oacc[nt][1] * inv0;
        float v10 = oacc[nt][2] * inv1, v11 = oacc[nt][3] * inv1;
        __nv_bfloat16 h00 = __float2bfloat16(v00);
        __nv_bfloat16 h01 = __float2bfloat16(v01);
        __nv_bfloat16 h10 = __float2bfloat16(v10);
        __nv_bfloat16 h11 = __float2bfloat16(v11);
        *(__nv_bfloat162*)(Oh + row0 + c) = __nv_bfloat162(h00, h01);
        *(__nv_bfloat162*)(Oh + row1 + c) = __nv_bfloat162(h10, h11);
        *(__nv_bfloat162*)(Ol + row0 + c) = __nv_bfloat162(
            __float2bfloat16(v00 - __bfloat162float(h00)),
            __float2bfloat16(v01 - __bfloat162float(h01)));
        *(__nv_bfloat162*)(Ol + row1 + c) = __nv_bfloat162(
            __float2bfloat16(v10 - __bfloat162float(h10)),
            __float2bfloat16(v11 - __bfloat162float(h11)));
    }
}

// ---------------------------------------------------------------------------
extern "C" void kernel_launch(void* const* d_in, const int* in_sizes, int n_in,
                              void* d_out, int out_size)
{
    const float* x  = (const float*)d_in[0];
    const float* Wq = (const float*)d_in[1];
    const float* bq = (const float*)d_in[2];
    const float* Wk = (const float*)d_in[3];
    const float* bk = (const float*)d_in[4];
    const float* Wv = (const float*)d_in[5];
    const float* bv = (const float*)d_in[6];
    const float* Wo = (const float*)d_in[7];
    const float* bo = (const float*)d_in[8];
    float* out = (float*)d_out;

    __nv_bfloat16 *xh, *xl, *wqh, *wql, *wkh, *wkl, *wvh, *wvl, *woh, *wol;
    __nv_bfloat16 *qh, *ql, *kh, *kl, *vh, *vl, *ah, *al;
    cudaGetSymbolAddress((void**)&xh, g_xh);
    cudaGetSymbolAddress((void**)&xl, g_xl);
    cudaGetSymbolAddress((void**)&wqh, g_wqh);
    cudaGetSymbolAddress((void**)&wql, g_wql);
    cudaGetSymbolAddress((void**)&wkh, g_wkh);
    cudaGetSymbolAddress((void**)&wkl, g_wkl);
    cudaGetSymbolAddress((void**)&wvh, g_wvh);
    cudaGetSymbolAddress((void**)&wvl, g_wvl);
    cudaGetSymbolAddress((void**)&woh, g_woh);
    cudaGetSymbolAddress((void**)&wol, g_wol);
    cudaGetSymbolAddress((void**)&qh, g_qh);
    cudaGetSymbolAddress((void**)&ql, g_ql);
    cudaGetSymbolAddress((void**)&kh, g_kh);
    cudaGetSymbolAddress((void**)&kl, g_kl);
    cudaGetSymbolAddress((void**)&vh, g_vh);
    cudaGetSymbolAddress((void**)&vl, g_vl);
    cudaGetSymbolAddress((void**)&ah, g_ah);
    cudaGetSymbolAddress((void**)&al, g_al);

    cudaFuncSetAttribute(gemm_qkv,
                         cudaFuncAttributeMaxDynamicSharedMemorySize,
                         GEMM_SMEM_BYTES);
    cudaFuncSetAttribute(gemm_out,
                         cudaFuncAttributeMaxDynamicSharedMemorySize,
                         GEMM_SMEM_BYTES);
    cudaFuncSetAttribute(attn_mma,
                         cudaFuncAttributeMaxDynamicSharedMemorySize,
                         ATT_SMEM_BYTES);

    // split inputs into hi/lo bf16
    {
        int n;
        n = MROWS * D_MODEL;   split_f32<<<n / 4 / 256, 256>>>(x,  xh,  xl,  n);
        n = D_MODEL * D_MODEL; split_f32<<<n / 4 / 256, 256>>>(Wq, wqh, wql, n);
        n = D_MODEL * D_KV;    split_f32<<<n / 4 / 256, 256>>>(Wk, wkh, wkl, n);
        n = D_MODEL * D_KV;    split_f32<<<n / 4 / 256, 256>>>(Wv, wvh, wvl, n);
        n = D_MODEL * D_MODEL; split_f32<<<n / 4 / 256, 256>>>(Wo, woh, wol, n);
    }

    // fused QKV projections -> bf16 hi/lo
    gemm_qkv<<<dim3(24, MROWS / BM), 256, GEMM_SMEM_BYTES>>>(
        xh, xl, wqh, wql, wkh, wkl, wvh, wvl, bq, bk, bv,
        qh, ql, kh, kl, vh, vl);

    // fused causal GQA attention (Br=64, Bc=32, 2 CTAs/SM)
    attn_mma<<<dim3(TSEQ / 64, HQ, BATCH), 128, ATT_SMEM_BYTES>>>(
        qh, ql, kh, kl, vh, vl, ah, al);

    // output projection -> fp32 out
    gemm_out<<<dim3(D_MODEL / BN, MROWS / BM), 256, GEMM_SMEM_BYTES>>>(
        ah, al, woh, wol, bo, out);
}